// round 12
// baseline (speedup 1.0000x reference)
#include <cuda_runtime.h>
#include <math.h>

#define B_   2
#define T_   2048
#define S_   2048
#define E_   1024
#define H_   16
#define DH_  64
#define SCALE_ 0.125f
#define CLAMP_V 50000.0f
#define NBLK 16              // S_/128 stat blocks per row (pass 1)

// Scratch (device globals: no allocations allowed)
__device__ float  g_Qp[B_ * T_ * E_];
__device__ float  g_Kp[B_ * S_ * E_];
__device__ float  g_Vp[B_ * S_ * E_];
__device__ float  g_ctx[B_ * T_ * E_];
__device__ float2 g_part[(size_t)B_ * H_ * T_ * NBLK];
// tf32-rounded copies of inputs + weights
__device__ float  g_qc[B_ * T_ * E_];
__device__ float  g_kc[B_ * S_ * E_];
__device__ float  g_vc[B_ * S_ * E_];
__device__ float  g_wc[4][E_ * E_];

// ---------------------------------------------------------------------------
__device__ __forceinline__ unsigned smem_u32(const void* p) {
    unsigned r;
    asm("{ .reg .u64 t; cvta.to.shared.u64 t, %1; cvt.u32.u64 %0, t; }"
        : "=r"(r) : "l"(p));
    return r;
}

#define CP16(d, s) \
    asm volatile("cp.async.cg.shared.global [%0], [%1], 16;" :: "r"(d), "l"(s))
#define CP_COMMIT() asm volatile("cp.async.commit_group;" ::: "memory")
#define CP_WAIT(n)  asm volatile("cp.async.wait_group %0;" :: "n"(n) : "memory")

__device__ __forceinline__ unsigned cvt_tf32(float x) {
    unsigned r;
    asm("cvt.rna.tf32.f32 %0, %1;" : "=r"(r) : "f"(x));
    return r;
}
__device__ __forceinline__ float tf32f(float x) {
    return __uint_as_float(cvt_tf32(x));
}

__device__ __forceinline__ void mma8(float* d, const unsigned* a, const unsigned* b) {
    asm volatile(
        "mma.sync.aligned.m16n8k8.row.col.f32.tf32.tf32.f32 "
        "{%0,%1,%2,%3}, {%4,%5,%6,%7}, {%8,%9}, {%0,%1,%2,%3};"
        : "+f"(d[0]), "+f"(d[1]), "+f"(d[2]), "+f"(d[3])
        : "r"(a[0]), "r"(a[1]), "r"(a[2]), "r"(a[3]), "r"(b[0]), "r"(b[1]));
}

__device__ __forceinline__ void softmax_merge(float& m, float& s, float om, float os) {
    float nm = fmaxf(m, om);
    if (nm == -INFINITY) { m = nm; s = 0.f; return; }
    s = s * __expf(m - nm) + os * __expf(om - nm);
    m = nm;
}

// Fragment compute from PRE-ROUNDED tf32 row-major smem (pad 20). NO cvt.
#define K8_RAW(As_, Bs_, kk, mbase, nbase, acc)                            \
    do {                                                                   \
        unsigned af[4][4], bf[4][2];                                       \
        _Pragma("unroll")                                                  \
        for (int i = 0; i < 4; i++) {                                      \
            int mr = (mbase) + i * 16 + lr;                                \
            af[i][0] = __float_as_uint((As_)[mr][(kk) + lc]);              \
            af[i][1] = __float_as_uint((As_)[mr + 8][(kk) + lc]);          \
            af[i][2] = __float_as_uint((As_)[mr][(kk) + 4 + lc]);          \
            af[i][3] = __float_as_uint((As_)[mr + 8][(kk) + 4 + lc]);      \
        }                                                                  \
        _Pragma("unroll")                                                  \
        for (int j = 0; j < 4; j++) {                                      \
            int nr = (nbase) + j * 8 + lr;                                 \
            bf[j][0] = __float_as_uint((Bs_)[nr][(kk) + lc]);              \
            bf[j][1] = __float_as_uint((Bs_)[nr][(kk) + 4 + lc]);          \
        }                                                                  \
        _Pragma("unroll")                                                  \
        for (int i = 0; i < 4; i++)                                        \
            _Pragma("unroll")                                              \
            for (int j = 0; j < 4; j++)                                    \
                mma8(acc[i][j], af[i], bf[j]);                             \
    } while (0)

struct GemmArgs {
    const float* A[3];
    const float* W[3];
    const float* bias[3];
    float*       C[3];
    float        alpha[3];
    int          rnd[3];     // 1 -> round output to tf32
};

struct CvtArgs {
    const float* src[4];
    float*       dst[4];
};

// ---------------------------------------------------------------------------
// Elementwise RNA tf32 rounding: dst[z] = tf32(src[z]).  float4 grid-stride.
// ---------------------------------------------------------------------------
__global__ __launch_bounds__(256) void cvt_tf32_batch(CvtArgs ca, int n4)
{
    const float4* s = (const float4*)ca.src[blockIdx.z];
    float4*       d = (float4*)ca.dst[blockIdx.z];
    for (int i = blockIdx.x * 256 + threadIdx.x; i < n4; i += gridDim.x * 256) {
        float4 v = s[i];
        v.x = tf32f(v.x); v.y = tf32f(v.y);
        v.z = tf32f(v.z); v.w = tf32f(v.w);
        d[i] = v;
    }
}

// ---------------------------------------------------------------------------
// NT GEMM + bias + alpha.  BM=BN=128, BK=16, 256 thr, 8 warps (2m x 4n),
// warp tile 64x32.  cp.async 2-stage, pre-rounded tf32 data (no cvt in loop).
// ---------------------------------------------------------------------------
__global__ __launch_bounds__(256) void gemm_nt_bias(
    GemmArgs ga, int K, int lda, int ldb, int ldc)
{
    const int z = blockIdx.z;
    const float* A    = ga.A[z];
    const float* Bm   = ga.W[z];
    const float* bias = ga.bias[z];
    float*       C    = ga.C[z];
    const float  alpha = ga.alpha[z];
    const int    rnd   = ga.rnd[z];

    __shared__ float As[2][128][20];
    __shared__ float Bs[2][128][20];

    const int tid = threadIdx.x;
    const int lane = tid & 31, w = tid >> 5;
    const int wm = w & 1, wn = w >> 1;
    const int lr = lane >> 2, lc = lane & 3;
    const int bm = blockIdx.y * 128, bn = blockIdx.x * 128;
    const int row = tid >> 1, half = tid & 1;

    const float* Ag = A + (size_t)(bm + row) * lda + half * 8;
    const float* Bg = Bm + (size_t)(bn + row) * ldb + half * 8;
    const unsigned daBase = smem_u32(&As[0][row][half * 8]);
    const unsigned dbBase = smem_u32(&Bs[0][row][half * 8]);
    const unsigned bufStride = 128 * 20 * 4;

#define G_STAGE(kc, buf)                                                   \
    do {                                                                   \
        unsigned da = daBase + (buf) * bufStride;                          \
        unsigned db = dbBase + (buf) * bufStride;                          \
        CP16(da,      Ag + (kc) * 16);                                     \
        CP16(da + 16, Ag + (kc) * 16 + 4);                                 \
        CP16(db,      Bg + (kc) * 16);                                     \
        CP16(db + 16, Bg + (kc) * 16 + 4);                                 \
        CP_COMMIT();                                                       \
    } while (0)

    float acc[4][4][4] = {};

    const int NC = K >> 4;
    G_STAGE(0, 0);
    G_STAGE(1, 1);

    for (int kc = 0; kc < NC; kc++) {
        const int buf = kc & 1;
        if (kc + 1 < NC) CP_WAIT(1); else CP_WAIT(0);
        __syncthreads();
        K8_RAW(As[buf], Bs[buf], 0, wm * 64, wn * 32, acc);
        K8_RAW(As[buf], Bs[buf], 8, wm * 64, wn * 32, acc);
        __syncthreads();
        if (kc + 2 < NC) G_STAGE(kc + 2, buf);
    }
#undef G_STAGE

#pragma unroll
    for (int j = 0; j < 4; j++) {
        int col = bn + wn * 32 + j * 8 + lc * 2;
        float b0v = bias[col], b1v = bias[col + 1];
#pragma unroll
        for (int i = 0; i < 4; i++) {
            int r0 = bm + wm * 64 + i * 16 + lr;
            float o00 = alpha * (acc[i][j][0] + b0v);
            float o01 = alpha * (acc[i][j][1] + b1v);
            float o10 = alpha * (acc[i][j][2] + b0v);
            float o11 = alpha * (acc[i][j][3] + b1v);
            if (rnd) {
                o00 = tf32f(o00); o01 = tf32f(o01);
                o10 = tf32f(o10); o11 = tf32f(o11);
            }
            *(float2*)(C + (size_t)r0 * ldc + col)       = make_float2(o00, o01);
            *(float2*)(C + (size_t)(r0 + 8) * ldc + col) = make_float2(o10, o11);
        }
    }
}

// ---------------------------------------------------------------------------
// Pass 1 — stats only: per (b,h) 128x128 tile of clamp(Q.K^T)+mask,
// emits per-(row, block) (m, s) to part.  Q/K pre-rounded -> no cvt.
// ---------------------------------------------------------------------------
__global__ __launch_bounds__(256) void attn_stats(
    const float* __restrict__ Qp, const float* __restrict__ Kp,
    const int* __restrict__ mask, float2* __restrict__ part)
{
    __shared__ float As[2][128][20];
    __shared__ float Bs[2][128][20];
    __shared__ float red_m[4][128];
    __shared__ float red_s[4][128];
    __shared__ int msk[128];

    const int bh = blockIdx.z, b = bh >> 4, h = bh & 15;

    const int tid = threadIdx.x;
    const int lane = tid & 31, w = tid >> 5;
    const int wm = w & 1, wn = w >> 1;
    const int lr = lane >> 2, lc = lane & 3;
    const int bm = blockIdx.y * 128, bn = blockIdx.x * 128;
    const int row = tid >> 1, half = tid & 1;

    const float* Ag = Qp + (size_t)b * T_ * E_ + (size_t)(bm + row) * E_ + h * DH_ + half * 8;
    const float* Bg = Kp + (size_t)b * S_ * E_ + (size_t)(bn + row) * E_ + h * DH_ + half * 8;
    const unsigned daBase = smem_u32(&As[0][row][half * 8]);
    const unsigned dbBase = smem_u32(&Bs[0][row][half * 8]);
    const unsigned bufStride = 128 * 20 * 4;

#define S_STAGE(kc, buf)                                                   \
    do {                                                                   \
        unsigned da = daBase + (buf) * bufStride;                          \
        unsigned db = dbBase + (buf) * bufStride;                          \
        CP16(da,      Ag + (kc) * 16);                                     \
        CP16(da + 16, Ag + (kc) * 16 + 4);                                 \
        CP16(db,      Bg + (kc) * 16);                                     \
        CP16(db + 16, Bg + (kc) * 16 + 4);                                 \
        CP_COMMIT();                                                       \
    } while (0)

    if (tid < 128) msk[tid] = mask[(size_t)b * S_ + bn + tid];

    float acc[4][4][4] = {};

    S_STAGE(0, 0);
    S_STAGE(1, 1);

#pragma unroll
    for (int kc = 0; kc < 4; kc++) {
        const int buf = kc & 1;
        if (kc < 3) CP_WAIT(1); else CP_WAIT(0);
        __syncthreads();
        K8_RAW(As[buf], Bs[buf], 0, wm * 64, wn * 32, acc);
        K8_RAW(As[buf], Bs[buf], 8, wm * 64, wn * 32, acc);
        __syncthreads();
        if (kc < 2) S_STAGE(kc + 2, buf);
    }
#undef S_STAGE

#define SCV(i, j, idx, keep) \
    ((keep) ? fminf(fmaxf(acc[i][j][idx], -CLAMP_V), CLAMP_V) : -INFINITY)

#pragma unroll
    for (int i = 0; i < 4; i++) {
        int rl = wm * 64 + i * 16 + lr;
        float m_lo = -INFINITY, m_hi = -INFINITY;
#pragma unroll
        for (int j = 0; j < 4; j++) {
            int lcol = wn * 32 + j * 8 + lc * 2;
            bool k0 = msk[lcol] != 0, k1 = msk[lcol + 1] != 0;
            m_lo = fmaxf(m_lo, fmaxf(SCV(i, j, 0, k0), SCV(i, j, 1, k1)));
            m_hi = fmaxf(m_hi, fmaxf(SCV(i, j, 2, k0), SCV(i, j, 3, k1)));
        }
#pragma unroll
        for (int off = 1; off <= 2; off <<= 1) {
            m_lo = fmaxf(m_lo, __shfl_xor_sync(0xffffffffu, m_lo, off));
            m_hi = fmaxf(m_hi, __shfl_xor_sync(0xffffffffu, m_hi, off));
        }
        if (lc == 0) {
            red_m[wn][rl]     = m_lo;
            red_m[wn][rl + 8] = m_hi;
        }
    }
    __syncthreads();

#pragma unroll
    for (int i = 0; i < 4; i++) {
        int rl = wm * 64 + i * 16 + lr;
        float mlo = fmaxf(fmaxf(red_m[0][rl], red_m[1][rl]),
                          fmaxf(red_m[2][rl], red_m[3][rl]));
        float mhi = fmaxf(fmaxf(red_m[0][rl + 8], red_m[1][rl + 8]),
                          fmaxf(red_m[2][rl + 8], red_m[3][rl + 8]));
        float mlou = (mlo == -INFINITY) ? 0.f : mlo;
        float mhiu = (mhi == -INFINITY) ? 0.f : mhi;
        float s_lo = 0.f, s_hi = 0.f;
#pragma unroll
        for (int j = 0; j < 4; j++) {
            int lcol = wn * 32 + j * 8 + lc * 2;
            bool k0 = msk[lcol] != 0, k1 = msk[lcol + 1] != 0;
            s_lo += __expf(SCV(i, j, 0, k0) - mlou) + __expf(SCV(i, j, 1, k1) - mlou);
            s_hi += __expf(SCV(i, j, 2, k0) - mhiu) + __expf(SCV(i, j, 3, k1) - mhiu);
        }
#pragma unroll
        for (int off = 1; off <= 2; off <<= 1) {
            s_lo += __shfl_xor_sync(0xffffffffu, s_lo, off);
            s_hi += __shfl_xor_sync(0xffffffffu, s_hi, off);
        }
        if (lc == 0) {
            red_s[wn][rl]     = s_lo;
            red_s[wn][rl + 8] = s_hi;
        }
    }
    __syncthreads();

    if (tid < 128) {
        float m = fmaxf(fmaxf(red_m[0][tid], red_m[1][tid]),
                        fmaxf(red_m[2][tid], red_m[3][tid]));
        float s = red_s[0][tid] + red_s[1][tid] + red_s[2][tid] + red_s[3][tid];
        part[((size_t)bh * T_ + bm + tid) * NBLK + blockIdx.x] = make_float2(m, s);
    }
#undef SCV
}

// ---------------------------------------------------------------------------
// Pass 2 — fused (R10 structure): recompute QK^T per 64-col block,
// p = exp(clamp(v) - m_glob)*inv (mask->0), write p to attn ONCE, Ps smem
// bounce (tf32), Ctx += P @ V.  Q/K/V pre-rounded -> no cvt on their loads.
// Layout (floats): Q[128][68] | Ps[64][136] | Ks[2][64][20] | Vs[64][72] |
//                  st float2[128] | mk char[2048]
// ---------------------------------------------------------------------------
#define FZ_Q  0
#define FZ_P  8704
#define FZ_K  17408
#define FZ_V  19968
#define FZ_ST 24576
#define FZ_MK 24832
#define FZ_TOT 25344

__global__ __launch_bounds__(256, 2) void attn_fused(
    const float* __restrict__ Qp, const float* __restrict__ Kp,
    const float* __restrict__ Vp, const int* __restrict__ mask,
    const float2* __restrict__ part, float* __restrict__ P,
    float* __restrict__ Ctx)
{
    extern __shared__ float sm[];
    const int bh = blockIdx.y, b = bh >> 4, h = bh & 15;
    const int tid = threadIdx.x;
    const int lane = tid & 31, w = tid >> 5;
    const int wm = w & 1, wn = w >> 1;
    const int lr = lane >> 2, lc = lane & 3;
    const int bm = blockIdx.x * 128;
    const unsigned smb = smem_u32(sm);

    // row stats: merge 16 block partials -> (m_glob, 1/s)
    if (tid < 128) {
        float m = -INFINITY, s = 0.f;
#pragma unroll
        for (int j = 0; j < NBLK; j++) {
            float2 p = part[((size_t)bh * T_ + bm + tid) * NBLK + j];
            softmax_merge(m, s, p.x, p.y);
        }
        ((float2*)(sm + FZ_ST))[tid] = make_float2(m, 1.f / s);
    }
    // mask bytes for all S
    {
        char* mk = (char*)(sm + FZ_MK);
        const int* mg = mask + (size_t)b * S_;
#pragma unroll
        for (int u = 0; u < 8; u++) {
            int i = u * 256 + tid;
            mk[i] = (mg[i] != 0);
        }
    }
    // stage Q (rows bm..bm+127, 64 k) raw row-major [128][68]
    {
        const float* Qg = Qp + (size_t)b * T_ * E_ + (size_t)bm * E_ + h * DH_;
#pragma unroll
        for (int u = 0; u < 8; u++) {
            int lin = u * 256 + tid;
            int row = lin >> 4, seg = lin & 15;
            CP16(smb + (FZ_Q + row * 68 + seg * 4) * 4,
                 Qg + (size_t)row * E_ + seg * 4);
        }
        CP_COMMIT();
    }
    __syncthreads();   // stats + mask visible

    const float* Kg = Kp + (size_t)b * S_ * E_ + h * DH_;
    const float* Vg = Vp + (size_t)b * S_ * E_ + h * DH_;
    float* Pg = P + (size_t)bh * T_ * S_;
    const float2* st = (const float2*)(sm + FZ_ST);
    const char* mk = (const char*)(sm + FZ_MK);

    float acc_c[4][2][4] = {};

    for (int cb = 0; cb < 32; cb++) {
        float acc_s[4][2][4] = {};
        // stage V block (64 s-rows x 64 d) raw [64][72]
        {
#pragma unroll
            for (int u = 0; u < 4; u++) {
                int lin = u * 256 + tid;
                int row = lin >> 4, seg = lin & 15;
                CP16(smb + (FZ_V + row * 72 + seg * 4) * 4,
                     Vg + (size_t)(cb * 64 + row) * E_ + seg * 4);
            }
            CP_COMMIT();
        }
        // stage K chunks 0,1 (64 s-rows x 16 k each) raw [64][20]
        {
            int row = tid >> 2, seg = tid & 3;
            CP16(smb + (FZ_K + row * 20 + seg * 4) * 4,
                 Kg + (size_t)(cb * 64 + row) * E_ + seg * 4);
            CP_COMMIT();
            CP16(smb + (FZ_K + 1280 + row * 20 + seg * 4) * 4,
                 Kg + (size_t)(cb * 64 + row) * E_ + 16 + seg * 4);
            CP_COMMIT();
        }
        // scores: K = 64 in 4 chunks of 16
#pragma unroll
        for (int kc = 0; kc < 4; kc++) {
            if (kc < 3) CP_WAIT(1); else CP_WAIT(0);
            __syncthreads();
            const float* Qb = sm + FZ_Q;
            const float* Kb = sm + FZ_K + (kc & 1) * 1280;
#pragma unroll
            for (int kt = 0; kt < 2; kt++) {
                const int kk = kt * 8;
                unsigned af[4][4], bf[2][2];
#pragma unroll
                for (int i = 0; i < 4; i++) {
                    int mr = wm * 64 + i * 16 + lr;
                    af[i][0] = __float_as_uint(Qb[mr * 68 + kc * 16 + kk + lc]);
                    af[i][1] = __float_as_uint(Qb[(mr + 8) * 68 + kc * 16 + kk + lc]);
                    af[i][2] = __float_as_uint(Qb[mr * 68 + kc * 16 + kk + 4 + lc]);
                    af[i][3] = __float_as_uint(Qb[(mr + 8) * 68 + kc * 16 + kk + 4 + lc]);
                }
#pragma unroll
                for (int j = 0; j < 2; j++) {
                    int nb = wn * 16 + j * 8 + lr;
                    bf[j][0] = __float_as_uint(Kb[nb * 20 + kk + lc]);
                    bf[j][1] = __float_as_uint(Kb[nb * 20 + kk + 4 + lc]);
                }
#pragma unroll
                for (int i = 0; i < 4; i++)
#pragma unroll
                    for (int j = 0; j < 2; j++)
                        mma8(acc_s[i][j], af[i], bf[j]);
            }
            if (kc < 2) {
                __syncthreads();
                int row = tid >> 2, seg = tid & 3;
                CP16(smb + (FZ_K + (kc & 1) * 1280 + row * 20 + seg * 4) * 4,
                     Kg + (size_t)(cb * 64 + row) * E_ + (kc + 2) * 16 + seg * 4);
                CP_COMMIT();
            }
        }
        // epilogue: p = exp(clamp(v) - m)*inv (mask->0); write attn + Ps smem
        {
            float* Pb = sm + FZ_P;
#pragma unroll
            for (int i = 0; i < 4; i++) {
                int rl = wm * 64 + i * 16 + lr;
                float2 s0 = st[rl], s1 = st[rl + 8];
                float m0 = (s0.x == -INFINITY) ? 0.f : s0.x;
                float m1 = (s1.x == -INFINITY) ? 0.f : s1.x;
#pragma unroll
                for (int j = 0; j < 2; j++) {
                    int lcol = wn * 16 + j * 8 + lc * 2;
                    int gcol = cb * 64 + lcol;
                    bool k0 = mk[gcol] != 0, k1 = mk[gcol + 1] != 0;
                    float v00 = fminf(fmaxf(acc_s[i][j][0], -CLAMP_V), CLAMP_V);
                    float v01 = fminf(fmaxf(acc_s[i][j][1], -CLAMP_V), CLAMP_V);
                    float v10 = fminf(fmaxf(acc_s[i][j][2], -CLAMP_V), CLAMP_V);
                    float v11 = fminf(fmaxf(acc_s[i][j][3], -CLAMP_V), CLAMP_V);
                    float p00 = k0 ? __expf(v00 - m0) * s0.y : 0.f;
                    float p01 = k1 ? __expf(v01 - m0) * s0.y : 0.f;
                    float p10 = k0 ? __expf(v10 - m1) * s1.y : 0.f;
                    float p11 = k1 ? __expf(v11 - m1) * s1.y : 0.f;
                    *(float2*)(Pg + (size_t)(bm + rl) * S_ + gcol)     = make_float2(p00, p01);
                    *(float2*)(Pg + (size_t)(bm + rl + 8) * S_ + gcol) = make_float2(p10, p11);
                    Pb[lcol * 136 + rl]           = tf32f(p00);
                    Pb[(lcol + 1) * 136 + rl]     = tf32f(p01);
                    Pb[lcol * 136 + rl + 8]       = tf32f(p10);
                    Pb[(lcol + 1) * 136 + rl + 8] = tf32f(p11);
                }
            }
        }
        __syncthreads();
        // PV: Ctx += P(128x64) @ V(64x64), k = 64 from smem
        {
            const float* Pb = sm + FZ_P;
            const float* Vb = sm + FZ_V;
#pragma unroll
            for (int kt8 = 0; kt8 < 8; kt8++) {
                const int kk = kt8 * 8;
                unsigned af[4][4], bf[2][2];
#pragma unroll
                for (int i = 0; i < 4; i++) {
                    int mb = wm * 64 + i * 16 + lr;
                    af[i][0] = __float_as_uint(Pb[(kk + lc) * 136 + mb]);
                    af[i][1] = __float_as_uint(Pb[(kk + lc) * 136 + mb + 8]);
                    af[i][2] = __float_as_uint(Pb[(kk + 4 + lc) * 136 + mb]);
                    af[i][3] = __float_as_uint(Pb[(kk + 4 + lc) * 136 + mb + 8]);
                }
#pragma unroll
                for (int j = 0; j < 2; j++) {
                    int nb = wn * 16 + j * 8 + lr;
                    bf[j][0] = __float_as_uint(Vb[(kk + lc) * 72 + nb]);
                    bf[j][1] = __float_as_uint(Vb[(kk + 4 + lc) * 72 + nb]);
                }
#pragma unroll
                for (int i = 0; i < 4; i++)
#pragma unroll
                    for (int j = 0; j < 2; j++)
                        mma8(acc_c[i][j], af[i], bf[j]);
            }
        }
        __syncthreads();
    }

    // Ctx epilogue (tf32-rounded: feeds Wo GEMM with no cvt)
    {
        float* Cg = Ctx + (size_t)b * T_ * E_ + h * DH_;
#pragma unroll
        for (int j = 0; j < 2; j++) {
            int col = wn * 16 + j * 8 + lc * 2;
#pragma unroll
            for (int i = 0; i < 4; i++) {
                int r0 = bm + wm * 64 + i * 16 + lr;
                *(float2*)(Cg + (size_t)r0 * E_ + col) =
                    make_float2(tf32f(acc_c[i][j][0]), tf32f(acc_c[i][j][1]));
                *(float2*)(Cg + (size_t)(r0 + 8) * E_ + col) =
                    make_float2(tf32f(acc_c[i][j][2]), tf32f(acc_c[i][j][3]));
            }
        }
    }
}

// ---------------------------------------------------------------------------
extern "C" void kernel_launch(void* const* d_in, const int* in_sizes, int n_in,
                              void* d_out, int out_size)
{
    const float* q    = (const float*)d_in[0];
    const float* k    = (const float*)d_in[1];
    const float* v    = (const float*)d_in[2];
    const int*   mask = (const int*)d_in[3];
    const float* Wq   = (const float*)d_in[4];
    const float* bq   = (const float*)d_in[5];
    const float* Wk   = (const float*)d_in[6];
    const float* bk   = (const float*)d_in[7];
    const float* Wv   = (const float*)d_in[8];
    const float* bv   = (const float*)d_in[9];
    const float* Wo   = (const float*)d_in[10];
    const float* bo   = (const float*)d_in[11];

    float* out  = (float*)d_out;
    float* attn = out + (size_t)B_ * T_ * E_;

    float *Qp, *Kp, *Vp, *Ctx, *qc, *kc, *vc, *wc;
    float2 *part;
    cudaGetSymbolAddress((void**)&Qp, g_Qp);
    cudaGetSymbolAddress((void**)&Kp, g_Kp);
    cudaGetSymbolAddress((void**)&Vp, g_Vp);
    cudaGetSymbolAddress((void**)&Ctx, g_ctx);
    cudaGetSymbolAddress((void**)&part, g_part);
    cudaGetSymbolAddress((void**)&qc, g_qc);
    cudaGetSymbolAddress((void**)&kc, g_kc);
    cudaGetSymbolAddress((void**)&vc, g_vc);
    cudaGetSymbolAddress((void**)&wc, g_wc);

    cudaFuncSetAttribute(attn_fused,
                         cudaFuncAttributeMaxDynamicSharedMemorySize,
                         FZ_TOT * 4);

    // Pre-round inputs + weights to tf32 (RNA) once.
    {
        CvtArgs ci;
        ci.src[0] = q;  ci.dst[0] = qc;
        ci.src[1] = k;  ci.dst[1] = kc;
        ci.src[2] = v;  ci.dst[2] = vc;
        ci.src[3] = q;  ci.dst[3] = qc;       // unused lane
        cvt_tf32_batch<<<dim3(2048, 1, 3), 256>>>(ci, (B_ * T_ * E_) / 4);

        CvtArgs cw;
        cw.src[0] = Wq; cw.dst[0] = wc + 0 * (size_t)E_ * E_;
        cw.src[1] = Wk; cw.dst[1] = wc + 1 * (size_t)E_ * E_;
        cw.src[2] = Wv; cw.dst[2] = wc + 2 * (size_t)E_ * E_;
        cw.src[3] = Wo; cw.dst[3] = wc + 3 * (size_t)E_ * E_;
        cvt_tf32_batch<<<dim3(1024, 1, 4), 256>>>(cw, (E_ * E_) / 4);
    }

    dim3 gq(E_ / 128, (B_ * T_) / 128, 3);   // QKV fused: (8, 32, 3)
    GemmArgs g1;
    g1.A[0] = qc; g1.W[0] = wc + 0 * (size_t)E_ * E_; g1.bias[0] = bq; g1.C[0] = Qp; g1.alpha[0] = SCALE_; g1.rnd[0] = 1;
    g1.A[1] = kc; g1.W[1] = wc + 1 * (size_t)E_ * E_; g1.bias[1] = bk; g1.C[1] = Kp; g1.alpha[1] = 1.0f;  g1.rnd[1] = 1;
    g1.A[2] = vc; g1.W[2] = wc + 2 * (size_t)E_ * E_; g1.bias[2] = bv; g1.C[2] = Vp; g1.alpha[2] = 1.0f;  g1.rnd[2] = 1;
    gemm_nt_bias<<<gq, 256>>>(g1, E_, E_, E_, E_);

    attn_stats<<<dim3(S_ / 128, T_ / 128, B_ * H_), 256>>>(Qp, Kp, mask, part);

    attn_fused<<<dim3(T_ / 128, B_ * H_), 256, FZ_TOT * 4>>>(
        Qp, Kp, Vp, mask, part, attn, Ctx);

    GemmArgs g2;
    g2.A[0] = Ctx; g2.W[0] = wc + 3 * (size_t)E_ * E_; g2.bias[0] = bo; g2.C[0] = out; g2.alpha[0] = 1.0f; g2.rnd[0] = 0;
    g2.A[1] = Ctx; g2.W[1] = wc + 3 * (size_t)E_ * E_; g2.bias[1] = bo; g2.C[1] = out; g2.alpha[1] = 1.0f; g2.rnd[1] = 0;
    g2.A[2] = Ctx; g2.W[2] = wc + 3 * (size_t)E_ * E_; g2.bias[2] = bo; g2.C[2] = out; g2.alpha[2] = 1.0f; g2.rnd[2] = 0;
    gemm_nt_bias<<<dim3(E_ / 128, (B_ * T_) / 128, 1), 256>>>(g2, E_, E_, E_, E_);
}

// round 14
// speedup vs baseline: 1.0543x; 1.0543x over previous
#include <cuda_runtime.h>
#include <math.h>

#define B_   2
#define T_   2048
#define S_   2048
#define E_   1024
#define H_   16
#define DH_  64
#define SCALE_ 0.125f
#define CLAMP_V 50000.0f
#define NBLK 16              // S_/128 stat blocks per row (pass 1)

// Scratch (device globals: no allocations allowed)
__device__ float  g_Qp[B_ * T_ * E_];
__device__ float  g_Kp[B_ * S_ * E_];
__device__ float  g_Vp[B_ * S_ * E_];
__device__ float  g_ctx[B_ * T_ * E_];
__device__ float2 g_part[(size_t)B_ * H_ * T_ * NBLK];

// ---------------------------------------------------------------------------
__device__ __forceinline__ unsigned smem_u32(const void* p) {
    unsigned r;
    asm("{ .reg .u64 t; cvta.to.shared.u64 t, %1; cvt.u32.u64 %0, t; }"
        : "=r"(r) : "l"(p));
    return r;
}

#define CP16(d, s) \
    asm volatile("cp.async.cg.shared.global [%0], [%1], 16;" :: "r"(d), "l"(s))
#define CP_COMMIT() asm volatile("cp.async.commit_group;" ::: "memory")
#define CP_WAIT(n)  asm volatile("cp.async.wait_group %0;" :: "n"(n) : "memory")

__device__ __forceinline__ unsigned cvt_tf32(float x) {
    unsigned r;
    asm("cvt.rna.tf32.f32 %0, %1;" : "=r"(r) : "f"(x));
    return r;
}
__device__ __forceinline__ float tf32f(float x) {
    return __uint_as_float(cvt_tf32(x));
}

__device__ __forceinline__ void mma8(float* d, const unsigned* a, const unsigned* b) {
    asm volatile(
        "mma.sync.aligned.m16n8k8.row.col.f32.tf32.tf32.f32 "
        "{%0,%1,%2,%3}, {%4,%5,%6,%7}, {%8,%9}, {%0,%1,%2,%3};"
        : "+f"(d[0]), "+f"(d[1]), "+f"(d[2]), "+f"(d[3])
        : "r"(a[0]), "r"(a[1]), "r"(a[2]), "r"(a[3]), "r"(b[0]), "r"(b[1]));
}

__device__ __forceinline__ void softmax_merge(float& m, float& s, float om, float os) {
    float nm = fmaxf(m, om);
    if (nm == -INFINITY) { m = nm; s = 0.f; return; }
    s = s * __expf(m - nm) + os * __expf(om - nm);
    m = nm;
}

// Fragment compute from RAW row-major smem (pad 20), cvt at load. 64x32 warp tile.
#define K8_RAW(As_, Bs_, kk, mbase, nbase, acc)                            \
    do {                                                                   \
        unsigned af[4][4], bf[4][2];                                       \
        _Pragma("unroll")                                                  \
        for (int i = 0; i < 4; i++) {                                      \
            int mr = (mbase) + i * 16 + lr;                                \
            af[i][0] = cvt_tf32((As_)[mr][(kk) + lc]);                     \
            af[i][1] = cvt_tf32((As_)[mr + 8][(kk) + lc]);                 \
            af[i][2] = cvt_tf32((As_)[mr][(kk) + 4 + lc]);                 \
            af[i][3] = cvt_tf32((As_)[mr + 8][(kk) + 4 + lc]);             \
        }                                                                  \
        _Pragma("unroll")                                                  \
        for (int j = 0; j < 4; j++) {                                      \
            int nr = (nbase) + j * 8 + lr;                                 \
            bf[j][0] = cvt_tf32((Bs_)[nr][(kk) + lc]);                     \
            bf[j][1] = cvt_tf32((Bs_)[nr][(kk) + 4 + lc]);                 \
        }                                                                  \
        _Pragma("unroll")                                                  \
        for (int i = 0; i < 4; i++)                                        \
            _Pragma("unroll")                                              \
            for (int j = 0; j < 4; j++)                                    \
                mma8(acc[i][j], af[i], bf[j]);                             \
    } while (0)

struct GemmArgs {
    const float* A[3];
    const float* W[3];
    const float* bias[3];
    float*       C[3];
    float        alpha[3];
};

// ---------------------------------------------------------------------------
// NT GEMM + bias + alpha (R10 version): BM=BN=128, BK=16, 256 thr,
// 8 warps (2m x 4n), warp tile 64x32, cp.async 2-stage, static smem.
// ---------------------------------------------------------------------------
__global__ __launch_bounds__(256) void gemm_nt_bias(
    GemmArgs ga, int K, int lda, int ldb, int ldc)
{
    const int z = blockIdx.z;
    const float* A    = ga.A[z];
    const float* Bm   = ga.W[z];
    const float* bias = ga.bias[z];
    float*       C    = ga.C[z];
    const float  alpha = ga.alpha[z];

    __shared__ float As[2][128][20];
    __shared__ float Bs[2][128][20];

    const int tid = threadIdx.x;
    const int lane = tid & 31, w = tid >> 5;
    const int wm = w & 1, wn = w >> 1;
    const int lr = lane >> 2, lc = lane & 3;
    const int bm = blockIdx.y * 128, bn = blockIdx.x * 128;
    const int row = tid >> 1, half = tid & 1;

    const float* Ag = A + (size_t)(bm + row) * lda + half * 8;
    const float* Bg = Bm + (size_t)(bn + row) * ldb + half * 8;
    const unsigned daBase = smem_u32(&As[0][row][half * 8]);
    const unsigned dbBase = smem_u32(&Bs[0][row][half * 8]);
    const unsigned bufStride = 128 * 20 * 4;

#define G_STAGE(kc, buf)                                                   \
    do {                                                                   \
        unsigned da = daBase + (buf) * bufStride;                          \
        unsigned db = dbBase + (buf) * bufStride;                          \
        CP16(da,      Ag + (kc) * 16);                                     \
        CP16(da + 16, Ag + (kc) * 16 + 4);                                 \
        CP16(db,      Bg + (kc) * 16);                                     \
        CP16(db + 16, Bg + (kc) * 16 + 4);                                 \
        CP_COMMIT();                                                       \
    } while (0)

    float acc[4][4][4] = {};

    const int NC = K >> 4;
    G_STAGE(0, 0);
    G_STAGE(1, 1);

    for (int kc = 0; kc < NC; kc++) {
        const int buf = kc & 1;
        if (kc + 1 < NC) CP_WAIT(1); else CP_WAIT(0);
        __syncthreads();
        K8_RAW(As[buf], Bs[buf], 0, wm * 64, wn * 32, acc);
        K8_RAW(As[buf], Bs[buf], 8, wm * 64, wn * 32, acc);
        __syncthreads();
        if (kc + 2 < NC) G_STAGE(kc + 2, buf);
    }
#undef G_STAGE

#pragma unroll
    for (int j = 0; j < 4; j++) {
        int col = bn + wn * 32 + j * 8 + lc * 2;
        float b0v = bias[col], b1v = bias[col + 1];
#pragma unroll
        for (int i = 0; i < 4; i++) {
            int r0 = bm + wm * 64 + i * 16 + lr;
            *(float2*)(C + (size_t)r0 * ldc + col) =
                make_float2(alpha * (acc[i][j][0] + b0v), alpha * (acc[i][j][1] + b1v));
            *(float2*)(C + (size_t)(r0 + 8) * ldc + col) =
                make_float2(alpha * (acc[i][j][2] + b0v), alpha * (acc[i][j][3] + b1v));
        }
    }
}

// ---------------------------------------------------------------------------
// Pass 1 — stats only (R10 version): per (b,h) 128x128 tile of
// clamp(Q.K^T)+mask, emits per-(row, block) (m, s).  No score stores.
// ---------------------------------------------------------------------------
__global__ __launch_bounds__(256) void attn_stats(
    const float* __restrict__ Qp, const float* __restrict__ Kp,
    const int* __restrict__ mask, float2* __restrict__ part)
{
    __shared__ float As[2][128][20];
    __shared__ float Bs[2][128][20];
    __shared__ float red_m[4][128];
    __shared__ float red_s[4][128];
    __shared__ int msk[128];

    const int bh = blockIdx.z, b = bh >> 4, h = bh & 15;

    const int tid = threadIdx.x;
    const int lane = tid & 31, w = tid >> 5;
    const int wm = w & 1, wn = w >> 1;
    const int lr = lane >> 2, lc = lane & 3;
    const int bm = blockIdx.y * 128, bn = blockIdx.x * 128;
    const int row = tid >> 1, half = tid & 1;

    const float* Ag = Qp + (size_t)b * T_ * E_ + (size_t)(bm + row) * E_ + h * DH_ + half * 8;
    const float* Bg = Kp + (size_t)b * S_ * E_ + (size_t)(bn + row) * E_ + h * DH_ + half * 8;
    const unsigned daBase = smem_u32(&As[0][row][half * 8]);
    const unsigned dbBase = smem_u32(&Bs[0][row][half * 8]);
    const unsigned bufStride = 128 * 20 * 4;

#define S_STAGE(kc, buf)                                                   \
    do {                                                                   \
        unsigned da = daBase + (buf) * bufStride;                          \
        unsigned db = dbBase + (buf) * bufStride;                          \
        CP16(da,      Ag + (kc) * 16);                                     \
        CP16(da + 16, Ag + (kc) * 16 + 4);                                 \
        CP16(db,      Bg + (kc) * 16);                                     \
        CP16(db + 16, Bg + (kc) * 16 + 4);                                 \
        CP_COMMIT();                                                       \
    } while (0)

    if (tid < 128) msk[tid] = mask[(size_t)b * S_ + bn + tid];

    float acc[4][4][4] = {};

    S_STAGE(0, 0);
    S_STAGE(1, 1);

#pragma unroll
    for (int kc = 0; kc < 4; kc++) {
        const int buf = kc & 1;
        if (kc < 3) CP_WAIT(1); else CP_WAIT(0);
        __syncthreads();
        K8_RAW(As[buf], Bs[buf], 0, wm * 64, wn * 32, acc);
        K8_RAW(As[buf], Bs[buf], 8, wm * 64, wn * 32, acc);
        __syncthreads();
        if (kc < 2) S_STAGE(kc + 2, buf);
    }
#undef S_STAGE

#define SCV(i, j, idx, keep) \
    ((keep) ? fminf(fmaxf(acc[i][j][idx], -CLAMP_V), CLAMP_V) : -INFINITY)

#pragma unroll
    for (int i = 0; i < 4; i++) {
        int rl = wm * 64 + i * 16 + lr;
        float m_lo = -INFINITY, m_hi = -INFINITY;
#pragma unroll
        for (int j = 0; j < 4; j++) {
            int lcol = wn * 32 + j * 8 + lc * 2;
            bool k0 = msk[lcol] != 0, k1 = msk[lcol + 1] != 0;
            m_lo = fmaxf(m_lo, fmaxf(SCV(i, j, 0, k0), SCV(i, j, 1, k1)));
            m_hi = fmaxf(m_hi, fmaxf(SCV(i, j, 2, k0), SCV(i, j, 3, k1)));
        }
#pragma unroll
        for (int off = 1; off <= 2; off <<= 1) {
            m_lo = fmaxf(m_lo, __shfl_xor_sync(0xffffffffu, m_lo, off));
            m_hi = fmaxf(m_hi, __shfl_xor_sync(0xffffffffu, m_hi, off));
        }
        if (lc == 0) {
            red_m[wn][rl]     = m_lo;
            red_m[wn][rl + 8] = m_hi;
        }
    }
    __syncthreads();

#pragma unroll
    for (int i = 0; i < 4; i++) {
        int rl = wm * 64 + i * 16 + lr;
        float mlo = fmaxf(fmaxf(red_m[0][rl], red_m[1][rl]),
                          fmaxf(red_m[2][rl], red_m[3][rl]));
        float mhi = fmaxf(fmaxf(red_m[0][rl + 8], red_m[1][rl + 8]),
                          fmaxf(red_m[2][rl + 8], red_m[3][rl + 8]));
        float mlou = (mlo == -INFINITY) ? 0.f : mlo;
        float mhiu = (mhi == -INFINITY) ? 0.f : mhi;
        float s_lo = 0.f, s_hi = 0.f;
#pragma unroll
        for (int j = 0; j < 4; j++) {
            int lcol = wn * 32 + j * 8 + lc * 2;
            bool k0 = msk[lcol] != 0, k1 = msk[lcol + 1] != 0;
            s_lo += __expf(SCV(i, j, 0, k0) - mlou) + __expf(SCV(i, j, 1, k1) - mlou);
            s_hi += __expf(SCV(i, j, 2, k0) - mhiu) + __expf(SCV(i, j, 3, k1) - mhiu);
        }
#pragma unroll
        for (int off = 1; off <= 2; off <<= 1) {
            s_lo += __shfl_xor_sync(0xffffffffu, s_lo, off);
            s_hi += __shfl_xor_sync(0xffffffffu, s_hi, off);
        }
        if (lc == 0) {
            red_s[wn][rl]     = s_lo;
            red_s[wn][rl + 8] = s_hi;
        }
    }
    __syncthreads();

    if (tid < 128) {
        float m = fmaxf(fmaxf(red_m[0][tid], red_m[1][tid]),
                        fmaxf(red_m[2][tid], red_m[3][tid]));
        float s = red_s[0][tid] + red_s[1][tid] + red_s[2][tid] + red_s[3][tid];
        part[((size_t)bh * T_ + bm + tid) * NBLK + blockIdx.x] = make_float2(m, s);
    }
#undef SCV
}

// ---------------------------------------------------------------------------
// Pass 2 — fused (R11 version): recompute QK^T per 64-col block with the full
// 64x64 K block staged once, p = exp(clamp(v)-m_glob)*inv (mask->0), write p
// to attn ONCE, Ps smem bounce (tf32), Ctx += P @ V.  3 syncs per col-block;
// next K prefetched behind PV.
// Layout (floats): Q[128][68] | Ps[64][136] | K[64][68] | V[64][72] |
//                  st float2[128] | mk char[2048]
// ---------------------------------------------------------------------------
#define FZ_Q  0
#define FZ_P  8704
#define FZ_K  17408
#define FZ_V  21760
#define FZ_ST 26368
#define FZ_MK 26624
#define FZ_TOT 27136

__global__ __launch_bounds__(256, 2) void attn_fused(
    const float* __restrict__ Qp, const float* __restrict__ Kp,
    const float* __restrict__ Vp, const int* __restrict__ mask,
    const float2* __restrict__ part, float* __restrict__ P,
    float* __restrict__ Ctx)
{
    extern __shared__ float sm[];
    const int bh = blockIdx.y, b = bh >> 4, h = bh & 15;
    const int tid = threadIdx.x;
    const int lane = tid & 31, w = tid >> 5;
    const int wm = w & 1, wn = w >> 1;
    const int lr = lane >> 2, lc = lane & 3;
    const int bm = blockIdx.x * 128;
    const unsigned smb = smem_u32(sm);

    // row stats: merge 16 block partials -> (m_glob, 1/s)
    if (tid < 128) {
        float m = -INFINITY, s = 0.f;
#pragma unroll
        for (int j = 0; j < NBLK; j++) {
            float2 p = part[((size_t)bh * T_ + bm + tid) * NBLK + j];
            softmax_merge(m, s, p.x, p.y);
        }
        ((float2*)(sm + FZ_ST))[tid] = make_float2(m, 1.f / s);
    }
    // mask bytes for all S
    {
        char* mk = (char*)(sm + FZ_MK);
        const int* mg = mask + (size_t)b * S_;
#pragma unroll
        for (int u = 0; u < 8; u++) {
            int i = u * 256 + tid;
            mk[i] = (mg[i] != 0);
        }
    }

    const float* Kg = Kp + (size_t)b * S_ * E_ + h * DH_;
    const float* Vg = Vp + (size_t)b * S_ * E_ + h * DH_;

#define STAGE_K(cb)                                                        \
    do {                                                                   \
        _Pragma("unroll")                                                  \
        for (int u = 0; u < 4; u++) {                                      \
            int lin = u * 256 + tid;                                       \
            int r_ = lin >> 4, sg = lin & 15;                              \
            CP16(smb + (FZ_K + r_ * 68 + sg * 4) * 4,                      \
                 Kg + (size_t)((cb) * 64 + r_) * E_ + sg * 4);             \
        }                                                                  \
        CP_COMMIT();                                                       \
    } while (0)

#define STAGE_V(cb)                                                        \
    do {                                                                   \
        _Pragma("unroll")                                                  \
        for (int u = 0; u < 4; u++) {                                      \
            int lin = u * 256 + tid;                                       \
            int r_ = lin >> 4, sg = lin & 15;                              \
            CP16(smb + (FZ_V + r_ * 72 + sg * 4) * 4,                      \
                 Vg + (size_t)((cb) * 64 + r_) * E_ + sg * 4);             \
        }                                                                  \
        CP_COMMIT();                                                       \
    } while (0)

    // stage Q (rows bm..bm+127, 64 k) raw row-major [128][68]
    {
        const float* Qg = Qp + (size_t)b * T_ * E_ + (size_t)bm * E_ + h * DH_;
#pragma unroll
        for (int u = 0; u < 8; u++) {
            int lin = u * 256 + tid;
            int r_ = lin >> 4, sg = lin & 15;
            CP16(smb + (FZ_Q + r_ * 68 + sg * 4) * 4,
                 Qg + (size_t)r_ * E_ + sg * 4);
        }
        CP_COMMIT();
    }
    STAGE_K(0);
    STAGE_V(0);

    float* Pg = P + (size_t)bh * T_ * S_;
    const float2* st = (const float2*)(sm + FZ_ST);
    const char* mk = (const char*)(sm + FZ_MK);

    float acc_c[4][2][4] = {};

    for (int cb = 0; cb < 32; cb++) {
        CP_WAIT(0);
        __syncthreads();   // Q(first), K(cb), V(cb), stats, mask all visible

        // scores: 8 k8 steps, K=64 resident
        float acc_s[4][2][4] = {};
        {
            const float* Qb = sm + FZ_Q;
            const float* Kb = sm + FZ_K;
#pragma unroll
            for (int kt = 0; kt < 8; kt++) {
                const int kk = kt * 8;
                unsigned af[4][4], bf[2][2];
#pragma unroll
                for (int i = 0; i < 4; i++) {
                    int mr = wm * 64 + i * 16 + lr;
                    af[i][0] = cvt_tf32(Qb[mr * 68 + kk + lc]);
                    af[i][1] = cvt_tf32(Qb[(mr + 8) * 68 + kk + lc]);
                    af[i][2] = cvt_tf32(Qb[mr * 68 + kk + 4 + lc]);
                    af[i][3] = cvt_tf32(Qb[(mr + 8) * 68 + kk + 4 + lc]);
                }
#pragma unroll
                for (int j = 0; j < 2; j++) {
                    int nb = wn * 16 + j * 8 + lr;
                    bf[j][0] = cvt_tf32(Kb[nb * 68 + kk + lc]);
                    bf[j][1] = cvt_tf32(Kb[nb * 68 + kk + 4 + lc]);
                }
#pragma unroll
                for (int i = 0; i < 4; i++)
#pragma unroll
                    for (int j = 0; j < 2; j++)
                        mma8(acc_s[i][j], af[i], bf[j]);
            }
        }

        // epilogue: p = exp(clamp(v)-m)*inv (mask->0); write attn + Ps smem
        {
            float* Pb = sm + FZ_P;
#pragma unroll
            for (int i = 0; i < 4; i++) {
                int rl = wm * 64 + i * 16 + lr;
                float2 s0 = st[rl], s1 = st[rl + 8];
                float m0 = (s0.x == -INFINITY) ? 0.f : s0.x;
                float m1 = (s1.x == -INFINITY) ? 0.f : s1.x;
#pragma unroll
                for (int j = 0; j < 2; j++) {
                    int lcol = wn * 16 + j * 8 + lc * 2;
                    int gcol = cb * 64 + lcol;
                    bool k0 = mk[gcol] != 0, k1 = mk[gcol + 1] != 0;
                    float v00 = fminf(fmaxf(acc_s[i][j][0], -CLAMP_V), CLAMP_V);
                    float v01 = fminf(fmaxf(acc_s[i][j][1], -CLAMP_V), CLAMP_V);
                    float v10 = fminf(fmaxf(acc_s[i][j][2], -CLAMP_V), CLAMP_V);
                    float v11 = fminf(fmaxf(acc_s[i][j][3], -CLAMP_V), CLAMP_V);
                    float p00 = k0 ? __expf(v00 - m0) * s0.y : 0.f;
                    float p01 = k1 ? __expf(v01 - m0) * s0.y : 0.f;
                    float p10 = k0 ? __expf(v10 - m1) * s1.y : 0.f;
                    float p11 = k1 ? __expf(v11 - m1) * s1.y : 0.f;
                    *(float2*)(Pg + (size_t)(bm + rl) * S_ + gcol)     = make_float2(p00, p01);
                    *(float2*)(Pg + (size_t)(bm + rl + 8) * S_ + gcol) = make_float2(p10, p11);
                    Pb[lcol * 136 + rl]           = tf32f(p00);
                    Pb[(lcol + 1) * 136 + rl]     = tf32f(p01);
                    Pb[lcol * 136 + rl + 8]       = tf32f(p10);
                    Pb[(lcol + 1) * 136 + rl + 8] = tf32f(p11);
                }
            }
        }
        __syncthreads();   // Ps ready; K region dead

        // prefetch next K behind PV
        if (cb + 1 < 32) STAGE_K(cb + 1);

        // PV: Ctx += P(128x64) @ V(64x64)
        {
            const float* Pb = sm + FZ_P;
            const float* Vb = sm + FZ_V;
#pragma unroll
            for (int kt8 = 0; kt8 < 8; kt8++) {
                const int kk = kt8 * 8;
                unsigned af[4][4], bf[2][2];
#pragma unroll
                for (int i = 0; i < 4; i++) {
                    int mb = wm * 64 + i * 16 + lr;
                    af[i][0] = __float_as_uint(Pb[(kk + lc) * 136 + mb]);
                    af[i][1] = __float_as_uint(Pb[(kk + lc) * 136 + mb + 8]);
                    af[i][2] = __float_as_uint(Pb[(kk + 4 + lc) * 136 + mb]);
                    af[i][3] = __float_as_uint(Pb[(kk + 4 + lc) * 136 + mb + 8]);
                }
#pragma unroll
                for (int j = 0; j < 2; j++) {
                    int nb = wn * 16 + j * 8 + lr;
                    bf[j][0] = cvt_tf32(Vb[(kk + lc) * 72 + nb]);
                    bf[j][1] = cvt_tf32(Vb[(kk + 4 + lc) * 72 + nb]);
                }
#pragma unroll
                for (int i = 0; i < 4; i++)
#pragma unroll
                    for (int j = 0; j < 2; j++)
                        mma8(acc_c[i][j], af[i], bf[j]);
            }
        }
        __syncthreads();   // V, Ps free

        if (cb + 1 < 32) STAGE_V(cb + 1);
    }
#undef STAGE_K
#undef STAGE_V

    // Ctx epilogue
    {
        float* Cg = Ctx + (size_t)b * T_ * E_ + h * DH_;
#pragma unroll
        for (int j = 0; j < 2; j++) {
            int col = wn * 16 + j * 8 + lc * 2;
#pragma unroll
            for (int i = 0; i < 4; i++) {
                int r0 = bm + wm * 64 + i * 16 + lr;
                *(float2*)(Cg + (size_t)r0 * E_ + col) =
                    make_float2(acc_c[i][j][0], acc_c[i][j][1]);
                *(float2*)(Cg + (size_t)(r0 + 8) * E_ + col) =
                    make_float2(acc_c[i][j][2], acc_c[i][j][3]);
            }
        }
    }
}

// ---------------------------------------------------------------------------
extern "C" void kernel_launch(void* const* d_in, const int* in_sizes, int n_in,
                              void* d_out, int out_size)
{
    const float* q    = (const float*)d_in[0];
    const float* k    = (const float*)d_in[1];
    const float* v    = (const float*)d_in[2];
    const int*   mask = (const int*)d_in[3];
    const float* Wq   = (const float*)d_in[4];
    const float* bq   = (const float*)d_in[5];
    const float* Wk   = (const float*)d_in[6];
    const float* bk   = (const float*)d_in[7];
    const float* Wv   = (const float*)d_in[8];
    const float* bv   = (const float*)d_in[9];
    const float* Wo   = (const float*)d_in[10];
    const float* bo   = (const float*)d_in[11];

    float* out  = (float*)d_out;
    float* attn = out + (size_t)B_ * T_ * E_;

    float *Qp, *Kp, *Vp, *Ctx;
    float2 *part;
    cudaGetSymbolAddress((void**)&Qp, g_Qp);
    cudaGetSymbolAddress((void**)&Kp, g_Kp);
    cudaGetSymbolAddress((void**)&Vp, g_Vp);
    cudaGetSymbolAddress((void**)&Ctx, g_ctx);
    cudaGetSymbolAddress((void**)&part, g_part);

    cudaFuncSetAttribute(attn_fused,
                         cudaFuncAttributeMaxDynamicSharedMemorySize,
                         FZ_TOT * 4);

    dim3 gq(E_ / 128, (B_ * T_) / 128, 3);   // QKV fused: (8, 32, 3)
    GemmArgs g1;
    g1.A[0] = q;  g1.W[0] = Wq; g1.bias[0] = bq; g1.C[0] = Qp; g1.alpha[0] = SCALE_;
    g1.A[1] = k;  g1.W[1] = Wk; g1.bias[1] = bk; g1.C[1] = Kp; g1.alpha[1] = 1.0f;
    g1.A[2] = v;  g1.W[2] = Wv; g1.bias[2] = bv; g1.C[2] = Vp; g1.alpha[2] = 1.0f;
    gemm_nt_bias<<<gq, 256>>>(g1, E_, E_, E_, E_);

    attn_stats<<<dim3(S_ / 128, T_ / 128, B_ * H_), 256>>>(Qp, Kp, mask, part);

    attn_fused<<<dim3(T_ / 128, B_ * H_), 256, FZ_TOT * 4>>>(
        Qp, Kp, Vp, mask, part, attn, Ctx);

    GemmArgs g2;
    g2.A[0] = Ctx; g2.W[0] = Wo; g2.bias[0] = bo; g2.C[0] = out; g2.alpha[0] = 1.0f;
    g2.A[1] = Ctx; g2.W[1] = Wo; g2.bias[1] = bo; g2.C[1] = out; g2.alpha[1] = 1.0f;
    g2.A[2] = Ctx; g2.W[2] = Wo; g2.bias[2] = bo; g2.C[2] = out; g2.alpha[2] = 1.0f;
    gemm_nt_bias<<<dim3(E_ / 128, (B_ * T_) / 128, 1), 256>>>(g2, E_, E_, E_, E_);
}

// round 15
// speedup vs baseline: 1.0603x; 1.0057x over previous
#include <cuda_runtime.h>
#include <math.h>

#define B_   2
#define T_   2048
#define S_   2048
#define E_   1024
#define H_   16
#define DH_  64
#define SCALE_ 0.125f
#define CLAMP_V 50000.0f

// Scratch (device globals: no allocations allowed)
__device__ float  g_Qp[B_ * T_ * E_];
__device__ float  g_Kp[B_ * S_ * E_];
__device__ float  g_Vp[B_ * S_ * E_];
__device__ float  g_ctx[B_ * T_ * E_];

// ---------------------------------------------------------------------------
__device__ __forceinline__ unsigned smem_u32(const void* p) {
    unsigned r;
    asm("{ .reg .u64 t; cvta.to.shared.u64 t, %1; cvt.u32.u64 %0, t; }"
        : "=r"(r) : "l"(p));
    return r;
}

#define CP16(d, s) \
    asm volatile("cp.async.cg.shared.global [%0], [%1], 16;" :: "r"(d), "l"(s))
#define CP_COMMIT() asm volatile("cp.async.commit_group;" ::: "memory")
#define CP_WAIT(n)  asm volatile("cp.async.wait_group %0;" :: "n"(n) : "memory")

__device__ __forceinline__ unsigned cvt_tf32(float x) {
    unsigned r;
    asm("cvt.rna.tf32.f32 %0, %1;" : "=r"(r) : "f"(x));
    return r;
}
__device__ __forceinline__ float tf32f(float x) {
    return __uint_as_float(cvt_tf32(x));
}

__device__ __forceinline__ void mma8(float* d, const unsigned* a, const unsigned* b) {
    asm volatile(
        "mma.sync.aligned.m16n8k8.row.col.f32.tf32.tf32.f32 "
        "{%0,%1,%2,%3}, {%4,%5,%6,%7}, {%8,%9}, {%0,%1,%2,%3};"
        : "+f"(d[0]), "+f"(d[1]), "+f"(d[2]), "+f"(d[3])
        : "r"(a[0]), "r"(a[1]), "r"(a[2]), "r"(a[3]), "r"(b[0]), "r"(b[1]));
}

__device__ __forceinline__ void softmax_merge(float& m, float& s, float om, float os) {
    float nm = fmaxf(m, om);
    if (nm == -INFINITY) { m = nm; s = 0.f; return; }
    s = s * __expf(m - nm) + os * __expf(om - nm);
    m = nm;
}

// Fragment compute from RAW row-major smem (pad 20), cvt at load. 64x32 warp tile.
#define K8_RAW(As_, Bs_, kk, mbase, nbase, acc)                            \
    do {                                                                   \
        unsigned af[4][4], bf[4][2];                                       \
        _Pragma("unroll")                                                  \
        for (int i = 0; i < 4; i++) {                                      \
            int mr = (mbase) + i * 16 + lr;                                \
            af[i][0] = cvt_tf32((As_)[mr][(kk) + lc]);                     \
            af[i][1] = cvt_tf32((As_)[mr + 8][(kk) + lc]);                 \
            af[i][2] = cvt_tf32((As_)[mr][(kk) + 4 + lc]);                 \
            af[i][3] = cvt_tf32((As_)[mr + 8][(kk) + 4 + lc]);             \
        }                                                                  \
        _Pragma("unroll")                                                  \
        for (int j = 0; j < 4; j++) {                                      \
            int nr = (nbase) + j * 8 + lr;                                 \
            bf[j][0] = cvt_tf32((Bs_)[nr][(kk) + lc]);                     \
            bf[j][1] = cvt_tf32((Bs_)[nr][(kk) + 4 + lc]);                 \
        }                                                                  \
        _Pragma("unroll")                                                  \
        for (int i = 0; i < 4; i++)                                        \
            _Pragma("unroll")                                              \
            for (int j = 0; j < 4; j++)                                    \
                mma8(acc[i][j], af[i], bf[j]);                             \
    } while (0)

struct GemmArgs {
    const float* A[3];
    const float* W[3];
    const float* bias[3];
    float*       C[3];
    float        alpha[3];
};

// ---------------------------------------------------------------------------
// NT GEMM + bias + alpha (R10/R14 version): BM=BN=128, BK=16, 256 thr,
// 8 warps (2m x 4n), warp tile 64x32, cp.async 2-stage, static smem.
// ---------------------------------------------------------------------------
__global__ __launch_bounds__(256) void gemm_nt_bias(
    GemmArgs ga, int K, int lda, int ldb, int ldc)
{
    const int z = blockIdx.z;
    const float* A    = ga.A[z];
    const float* Bm   = ga.W[z];
    const float* bias = ga.bias[z];
    float*       C    = ga.C[z];
    const float  alpha = ga.alpha[z];

    __shared__ float As[2][128][20];
    __shared__ float Bs[2][128][20];

    const int tid = threadIdx.x;
    const int lane = tid & 31, w = tid >> 5;
    const int wm = w & 1, wn = w >> 1;
    const int lr = lane >> 2, lc = lane & 3;
    const int bm = blockIdx.y * 128, bn = blockIdx.x * 128;
    const int row = tid >> 1, half = tid & 1;

    const float* Ag = A + (size_t)(bm + row) * lda + half * 8;
    const float* Bg = Bm + (size_t)(bn + row) * ldb + half * 8;
    const unsigned daBase = smem_u32(&As[0][row][half * 8]);
    const unsigned dbBase = smem_u32(&Bs[0][row][half * 8]);
    const unsigned bufStride = 128 * 20 * 4;

#define G_STAGE(kc, buf)                                                   \
    do {                                                                   \
        unsigned da = daBase + (buf) * bufStride;                          \
        unsigned db = dbBase + (buf) * bufStride;                          \
        CP16(da,      Ag + (kc) * 16);                                     \
        CP16(da + 16, Ag + (kc) * 16 + 4);                                 \
        CP16(db,      Bg + (kc) * 16);                                     \
        CP16(db + 16, Bg + (kc) * 16 + 4);                                 \
        CP_COMMIT();                                                       \
    } while (0)

    float acc[4][4][4] = {};

    const int NC = K >> 4;
    G_STAGE(0, 0);
    G_STAGE(1, 1);

    for (int kc = 0; kc < NC; kc++) {
        const int buf = kc & 1;
        if (kc + 1 < NC) CP_WAIT(1); else CP_WAIT(0);
        __syncthreads();
        K8_RAW(As[buf], Bs[buf], 0, wm * 64, wn * 32, acc);
        K8_RAW(As[buf], Bs[buf], 8, wm * 64, wn * 32, acc);
        __syncthreads();
        if (kc + 2 < NC) G_STAGE(kc + 2, buf);
    }
#undef G_STAGE

#pragma unroll
    for (int j = 0; j < 4; j++) {
        int col = bn + wn * 32 + j * 8 + lc * 2;
        float b0v = bias[col], b1v = bias[col + 1];
#pragma unroll
        for (int i = 0; i < 4; i++) {
            int r0 = bm + wm * 64 + i * 16 + lr;
            *(float2*)(C + (size_t)r0 * ldc + col) =
                make_float2(alpha * (acc[i][j][0] + b0v), alpha * (acc[i][j][1] + b1v));
            *(float2*)(C + (size_t)(r0 + 8) * ldc + col) =
                make_float2(alpha * (acc[i][j][2] + b0v), alpha * (acc[i][j][3] + b1v));
        }
    }
}

// ---------------------------------------------------------------------------
// Fused attention (stats phase absorbed):
// Phase 0: loop K blocks (double-buffered through the K+V smem regions),
//          recompute scores, online per-thread-strip (m, s) in registers.
//          Merge lanes/warps -> st[128] = (m_glob, 1/s).
// Phase 1: R14 loop — recompute scores, p = exp(clamp(v)-m)*inv (mask->0),
//          write p to attn once, Ps smem bounce, Ctx += P @ V.
// Layout (floats): Q[128][68] | Ps[64][136] | K[64][68] | V[64][72] |
//                  st float2[128] | mk char[2048]
// ---------------------------------------------------------------------------
#define FZ_Q  0
#define FZ_P  8704
#define FZ_K  17408
#define FZ_V  21760
#define FZ_ST 26368
#define FZ_MK 26624
#define FZ_TOT 27136

__global__ __launch_bounds__(256, 2) void attn_fused(
    const float* __restrict__ Qp, const float* __restrict__ Kp,
    const float* __restrict__ Vp, const int* __restrict__ mask,
    float* __restrict__ P, float* __restrict__ Ctx)
{
    extern __shared__ float sm[];
    const int bh = blockIdx.y, b = bh >> 4, h = bh & 15;
    const int tid = threadIdx.x;
    const int lane = tid & 31, w = tid >> 5;
    const int wm = w & 1, wn = w >> 1;
    const int lr = lane >> 2, lc = lane & 3;
    const int bm = blockIdx.x * 128;
    const unsigned smb = smem_u32(sm);

    // mask bytes for all S
    {
        char* mk = (char*)(sm + FZ_MK);
        const int* mg = mask + (size_t)b * S_;
#pragma unroll
        for (int u = 0; u < 8; u++) {
            int i = u * 256 + tid;
            mk[i] = (mg[i] != 0);
        }
    }

    const float* Kg = Kp + (size_t)b * S_ * E_ + h * DH_;
    const float* Vg = Vp + (size_t)b * S_ * E_ + h * DH_;

    // stage Q (rows bm..bm+127, 64 k) raw row-major [128][68]
    {
        const float* Qg = Qp + (size_t)b * T_ * E_ + (size_t)bm * E_ + h * DH_;
#pragma unroll
        for (int u = 0; u < 8; u++) {
            int lin = u * 256 + tid;
            int r_ = lin >> 4, sg = lin & 15;
            CP16(smb + (FZ_Q + r_ * 68 + sg * 4) * 4,
                 Qg + (size_t)r_ * E_ + sg * 4);
        }
        CP_COMMIT();
    }

    // generic 64x64 K-block stage into (off, stride)
#define STAGE_KB(cb, off, str)                                             \
    do {                                                                   \
        _Pragma("unroll")                                                  \
        for (int u = 0; u < 4; u++) {                                      \
            int lin = u * 256 + tid;                                       \
            int r_ = lin >> 4, sg = lin & 15;                              \
            CP16(smb + ((off) + r_ * (str) + sg * 4) * 4,                  \
                 Kg + (size_t)((cb) * 64 + r_) * E_ + sg * 4);             \
        }                                                                  \
        CP_COMMIT();                                                       \
    } while (0)

#define STAGE_V(cb)                                                        \
    do {                                                                   \
        _Pragma("unroll")                                                  \
        for (int u = 0; u < 4; u++) {                                      \
            int lin = u * 256 + tid;                                       \
            int r_ = lin >> 4, sg = lin & 15;                              \
            CP16(smb + (FZ_V + r_ * 72 + sg * 4) * 4,                      \
                 Vg + (size_t)((cb) * 64 + r_) * E_ + sg * 4);             \
        }                                                                  \
        CP_COMMIT();                                                       \
    } while (0)

    const char* mk = (const char*)(sm + FZ_MK);
    const float* Qb = sm + FZ_Q;

    // score MMA for one 64-col block: Kb/kstr parametrized
#define SCORE_MMA(Kb_, kstr_, accs)                                        \
    do {                                                                   \
        _Pragma("unroll")                                                  \
        for (int kt = 0; kt < 8; kt++) {                                   \
            const int kk = kt * 8;                                         \
            unsigned af[4][4], bf[2][2];                                   \
            _Pragma("unroll")                                              \
            for (int i = 0; i < 4; i++) {                                  \
                int mr = wm * 64 + i * 16 + lr;                            \
                af[i][0] = cvt_tf32(Qb[mr * 68 + kk + lc]);                \
                af[i][1] = cvt_tf32(Qb[(mr + 8) * 68 + kk + lc]);          \
                af[i][2] = cvt_tf32(Qb[mr * 68 + kk + 4 + lc]);            \
                af[i][3] = cvt_tf32(Qb[(mr + 8) * 68 + kk + 4 + lc]);      \
            }                                                              \
            _Pragma("unroll")                                              \
            for (int j = 0; j < 2; j++) {                                  \
                int nb = wn * 16 + j * 8 + lr;                             \
                bf[j][0] = cvt_tf32((Kb_)[nb * (kstr_) + kk + lc]);        \
                bf[j][1] = cvt_tf32((Kb_)[nb * (kstr_) + kk + 4 + lc]);    \
            }                                                              \
            _Pragma("unroll")                                              \
            for (int i = 0; i < 4; i++)                                    \
                _Pragma("unroll")                                          \
                for (int j = 0; j < 2; j++)                                \
                    mma8(accs[i][j], af[i], bf[j]);                        \
        }                                                                  \
    } while (0)

    // ------------------ Phase 0: stats (online, registers) ------------------
    STAGE_KB(0, FZ_K, 68);
    STAGE_KB(1, FZ_V, 72);

    float m_run[4][2], s_run[4][2];
#pragma unroll
    for (int i = 0; i < 4; i++) {
        m_run[i][0] = -INFINITY; m_run[i][1] = -INFINITY;
        s_run[i][0] = 0.f;       s_run[i][1] = 0.f;
    }

    for (int cb = 0; cb < 32; cb++) {
        CP_WAIT(1);
        __syncthreads();
        const float* Kb = sm + ((cb & 1) ? FZ_V : FZ_K);
        const int kstr  = (cb & 1) ? 72 : 68;

        float acc_s[4][2][4] = {};
        SCORE_MMA(Kb, kstr, acc_s);

        // online merge per thread strip
#pragma unroll
        for (int i = 0; i < 4; i++) {
#pragma unroll
            for (int hh = 0; hh < 2; hh++) {
                int lcol0 = wn * 16 + lc * 2;
                int g0 = cb * 64 + lcol0, g1 = cb * 64 + lcol0 + 8;
                bool k0 = mk[g0] != 0, k1 = mk[g0 + 1] != 0;
                bool k2 = mk[g1] != 0, k3 = mk[g1 + 1] != 0;
                float v0 = k0 ? fminf(fmaxf(acc_s[i][0][hh * 2],     -CLAMP_V), CLAMP_V) : -INFINITY;
                float v1 = k1 ? fminf(fmaxf(acc_s[i][0][hh * 2 + 1], -CLAMP_V), CLAMP_V) : -INFINITY;
                float v2 = k2 ? fminf(fmaxf(acc_s[i][1][hh * 2],     -CLAMP_V), CLAMP_V) : -INFINITY;
                float v3 = k3 ? fminf(fmaxf(acc_s[i][1][hh * 2 + 1], -CLAMP_V), CLAMP_V) : -INFINITY;
                float bmax = fmaxf(fmaxf(v0, v1), fmaxf(v2, v3));
                if (bmax != -INFINITY) {
                    float nm = fmaxf(m_run[i][hh], bmax);
                    float sc = (m_run[i][hh] == -INFINITY) ? 0.f
                               : s_run[i][hh] * __expf(m_run[i][hh] - nm);
                    s_run[i][hh] = sc + __expf(v0 - nm) + __expf(v1 - nm)
                                      + __expf(v2 - nm) + __expf(v3 - nm);
                    m_run[i][hh] = nm;
                }
            }
        }
        __syncthreads();
        if (cb + 2 < 32) STAGE_KB(cb + 2, (cb & 1) ? FZ_V : FZ_K, (cb & 1) ? 72 : 68);
    }
    CP_WAIT(0);

    // merge across lc lanes (shfl), then across wn warps (smem = Ps region)
    {
        float* red_m = sm + FZ_P;          // [4][128]
        float* red_s = sm + FZ_P + 512;    // [4][128]
#pragma unroll
        for (int i = 0; i < 4; i++) {
#pragma unroll
            for (int hh = 0; hh < 2; hh++) {
                float m = m_run[i][hh], s = s_run[i][hh];
#pragma unroll
                for (int off = 1; off <= 2; off <<= 1) {
                    softmax_merge(m, s, __shfl_xor_sync(0xffffffffu, m, off),
                                        __shfl_xor_sync(0xffffffffu, s, off));
                }
                if (lc == 0) {
                    int rl = wm * 64 + i * 16 + lr + hh * 8;
                    red_m[wn * 128 + rl] = m;
                    red_s[wn * 128 + rl] = s;
                }
            }
        }
        __syncthreads();
        if (tid < 128) {
            float m = red_m[tid], s = red_s[tid];
            softmax_merge(m, s, red_m[128 + tid], red_s[128 + tid]);
            softmax_merge(m, s, red_m[256 + tid], red_s[256 + tid]);
            softmax_merge(m, s, red_m[384 + tid], red_s[384 + tid]);
            ((float2*)(sm + FZ_ST))[tid] = make_float2(m, 1.f / s);
        }
        __syncthreads();
    }

    // ------------------ Phase 1: p-write + PV (R14 loop) --------------------
    STAGE_KB(0, FZ_K, 68);
    STAGE_V(0);

    float* Pg = P + (size_t)bh * T_ * S_;
    const float2* st = (const float2*)(sm + FZ_ST);

    float acc_c[4][2][4] = {};

    for (int cb = 0; cb < 32; cb++) {
        CP_WAIT(0);
        __syncthreads();

        float acc_s[4][2][4] = {};
        SCORE_MMA(sm + FZ_K, 68, acc_s);

        // epilogue: p = exp(clamp(v)-m)*inv (mask->0); write attn + Ps smem
        {
            float* Pb = sm + FZ_P;
#pragma unroll
            for (int i = 0; i < 4; i++) {
                int rl = wm * 64 + i * 16 + lr;
                float2 s0 = st[rl], s1 = st[rl + 8];
                float m0 = (s0.x == -INFINITY) ? 0.f : s0.x;
                float m1 = (s1.x == -INFINITY) ? 0.f : s1.x;
#pragma unroll
                for (int j = 0; j < 2; j++) {
                    int lcol = wn * 16 + j * 8 + lc * 2;
                    int gcol = cb * 64 + lcol;
                    bool k0 = mk[gcol] != 0, k1 = mk[gcol + 1] != 0;
                    float v00 = fminf(fmaxf(acc_s[i][j][0], -CLAMP_V), CLAMP_V);
                    float v01 = fminf(fmaxf(acc_s[i][j][1], -CLAMP_V), CLAMP_V);
                    float v10 = fminf(fmaxf(acc_s[i][j][2], -CLAMP_V), CLAMP_V);
                    float v11 = fminf(fmaxf(acc_s[i][j][3], -CLAMP_V), CLAMP_V);
                    float p00 = k0 ? __expf(v00 - m0) * s0.y : 0.f;
                    float p01 = k1 ? __expf(v01 - m0) * s0.y : 0.f;
                    float p10 = k0 ? __expf(v10 - m1) * s1.y : 0.f;
                    float p11 = k1 ? __expf(v11 - m1) * s1.y : 0.f;
                    *(float2*)(Pg + (size_t)(bm + rl) * S_ + gcol)     = make_float2(p00, p01);
                    *(float2*)(Pg + (size_t)(bm + rl + 8) * S_ + gcol) = make_float2(p10, p11);
                    Pb[lcol * 136 + rl]           = tf32f(p00);
                    Pb[(lcol + 1) * 136 + rl]     = tf32f(p01);
                    Pb[lcol * 136 + rl + 8]       = tf32f(p10);
                    Pb[(lcol + 1) * 136 + rl + 8] = tf32f(p11);
                }
            }
        }
        __syncthreads();   // Ps ready; K region dead

        if (cb + 1 < 32) STAGE_KB(cb + 1, FZ_K, 68);

        // PV: Ctx += P(128x64) @ V(64x64)
        {
            const float* Pb = sm + FZ_P;
            const float* Vb = sm + FZ_V;
#pragma unroll
            for (int kt8 = 0; kt8 < 8; kt8++) {
                const int kk = kt8 * 8;
                unsigned af[4][4], bf[2][2];
#pragma unroll
                for (int i = 0; i < 4; i++) {
                    int mb = wm * 64 + i * 16 + lr;
                    af[i][0] = __float_as_uint(Pb[(kk + lc) * 136 + mb]);
                    af[i][1] = __float_as_uint(Pb[(kk + lc) * 136 + mb + 8]);
                    af[i][2] = __float_as_uint(Pb[(kk + 4 + lc) * 136 + mb]);
                    af[i][3] = __float_as_uint(Pb[(kk + 4 + lc) * 136 + mb + 8]);
                }
#pragma unroll
                for (int j = 0; j < 2; j++) {
                    int nb = wn * 16 + j * 8 + lr;
                    bf[j][0] = cvt_tf32(Vb[(kk + lc) * 72 + nb]);
                    bf[j][1] = cvt_tf32(Vb[(kk + 4 + lc) * 72 + nb]);
                }
#pragma unroll
                for (int i = 0; i < 4; i++)
#pragma unroll
                    for (int j = 0; j < 2; j++)
                        mma8(acc_c[i][j], af[i], bf[j]);
            }
        }
        __syncthreads();   // V, Ps free

        if (cb + 1 < 32) STAGE_V(cb + 1);
    }
#undef STAGE_KB
#undef STAGE_V
#undef SCORE_MMA

    // Ctx epilogue
    {
        float* Cg = Ctx + (size_t)b * T_ * E_ + h * DH_;
#pragma unroll
        for (int j = 0; j < 2; j++) {
            int col = wn * 16 + j * 8 + lc * 2;
#pragma unroll
            for (int i = 0; i < 4; i++) {
                int r0 = bm + wm * 64 + i * 16 + lr;
                *(float2*)(Cg + (size_t)r0 * E_ + col) =
                    make_float2(acc_c[i][j][0], acc_c[i][j][1]);
                *(float2*)(Cg + (size_t)(r0 + 8) * E_ + col) =
                    make_float2(acc_c[i][j][2], acc_c[i][j][3]);
            }
        }
    }
}

// ---------------------------------------------------------------------------
extern "C" void kernel_launch(void* const* d_in, const int* in_sizes, int n_in,
                              void* d_out, int out_size)
{
    const float* q    = (const float*)d_in[0];
    const float* k    = (const float*)d_in[1];
    const float* v    = (const float*)d_in[2];
    const int*   mask = (const int*)d_in[3];
    const float* Wq   = (const float*)d_in[4];
    const float* bq   = (const float*)d_in[5];
    const float* Wk   = (const float*)d_in[6];
    const float* bk   = (const float*)d_in[7];
    const float* Wv   = (const float*)d_in[8];
    const float* bv   = (const float*)d_in[9];
    const float* Wo   = (const float*)d_in[10];
    const float* bo   = (const float*)d_in[11];

    float* out  = (float*)d_out;
    float* attn = out + (size_t)B_ * T_ * E_;

    float *Qp, *Kp, *Vp, *Ctx;
    cudaGetSymbolAddress((void**)&Qp, g_Qp);
    cudaGetSymbolAddress((void**)&Kp, g_Kp);
    cudaGetSymbolAddress((void**)&Vp, g_Vp);
    cudaGetSymbolAddress((void**)&Ctx, g_ctx);

    cudaFuncSetAttribute(attn_fused,
                         cudaFuncAttributeMaxDynamicSharedMemorySize,
                         FZ_TOT * 4);

    dim3 gq(E_ / 128, (B_ * T_) / 128, 3);   // QKV fused: (8, 32, 3)
    GemmArgs g1;
    g1.A[0] = q;  g1.W[0] = Wq; g1.bias[0] = bq; g1.C[0] = Qp; g1.alpha[0] = SCALE_;
    g1.A[1] = k;  g1.W[1] = Wk; g1.bias[1] = bk; g1.C[1] = Kp; g1.alpha[1] = 1.0f;
    g1.A[2] = v;  g1.W[2] = Wv; g1.bias[2] = bv; g1.C[2] = Vp; g1.alpha[2] = 1.0f;
    gemm_nt_bias<<<gq, 256>>>(g1, E_, E_, E_, E_);

    attn_fused<<<dim3(T_ / 128, B_ * H_), 256, FZ_TOT * 4>>>(
        Qp, Kp, Vp, mask, attn, Ctx);

    GemmArgs g2;
    g2.A[0] = Ctx; g2.W[0] = Wo; g2.bias[0] = bo; g2.C[0] = out; g2.alpha[0] = 1.0f;
    g2.A[1] = Ctx; g2.W[1] = Wo; g2.bias[1] = bo; g2.C[1] = out; g2.alpha[1] = 1.0f;
    g2.A[2] = Ctx; g2.W[2] = Wo; g2.bias[2] = bo; g2.C[2] = out; g2.alpha[2] = 1.0f;
    gemm_nt_bias<<<dim3(E_ / 128, (B_ * T_) / 128, 1), 256>>>(g2, E_, E_, E_, E_);
}

// round 16
// speedup vs baseline: 1.0628x; 1.0023x over previous
#include <cuda_runtime.h>
#include <math.h>

#define B_   2
#define T_   2048
#define S_   2048
#define E_   1024
#define H_   16
#define DH_  64
#define SCALE_ 0.125f
#define CLAMP_V 50000.0f

// Scratch (device globals: no allocations allowed)
__device__ float  g_Qp[B_ * T_ * E_];
__device__ float  g_Kp[B_ * S_ * E_];
__device__ float  g_Vp[B_ * S_ * E_];
__device__ float  g_ctx[B_ * T_ * E_];

// ---------------------------------------------------------------------------
__device__ __forceinline__ unsigned smem_u32(const void* p) {
    unsigned r;
    asm("{ .reg .u64 t; cvta.to.shared.u64 t, %1; cvt.u32.u64 %0, t; }"
        : "=r"(r) : "l"(p));
    return r;
}

#define CP16(d, s) \
    asm volatile("cp.async.cg.shared.global [%0], [%1], 16;" :: "r"(d), "l"(s))
#define CP_COMMIT() asm volatile("cp.async.commit_group;" ::: "memory")
#define CP_WAIT(n)  asm volatile("cp.async.wait_group %0;" :: "n"(n) : "memory")

__device__ __forceinline__ unsigned cvt_tf32(float x) {
    unsigned r;
    asm("cvt.rna.tf32.f32 %0, %1;" : "=r"(r) : "f"(x));
    return r;
}
__device__ __forceinline__ float tf32f(float x) {
    return __uint_as_float(cvt_tf32(x));
}

__device__ __forceinline__ void mma8(float* d, const unsigned* a, const unsigned* b) {
    asm volatile(
        "mma.sync.aligned.m16n8k8.row.col.f32.tf32.tf32.f32 "
        "{%0,%1,%2,%3}, {%4,%5,%6,%7}, {%8,%9}, {%0,%1,%2,%3};"
        : "+f"(d[0]), "+f"(d[1]), "+f"(d[2]), "+f"(d[3])
        : "r"(a[0]), "r"(a[1]), "r"(a[2]), "r"(a[3]), "r"(b[0]), "r"(b[1]));
}

__device__ __forceinline__ void softmax_merge(float& m, float& s, float om, float os) {
    float nm = fmaxf(m, om);
    if (nm == -INFINITY) { m = nm; s = 0.f; return; }
    s = s * __expf(m - nm) + os * __expf(om - nm);
    m = nm;
}

struct GemmArgs {
    const float* A[3];
    const float* W[3];
    const float* bias[3];
    float*       C[3];
    float        alpha[3];
};

// ---------------------------------------------------------------------------
// NT GEMM + bias + alpha.  BM=BN=128, BK=16, 256 thr, 8 warps (2m x 4n),
// warp tile 64x32.  3-stage cp.async, ONE sync per iteration (dynamic smem).
// ---------------------------------------------------------------------------
#define GQ_STRIDE 20
#define GQ_BUF    (128 * GQ_STRIDE)          // floats per buffer
#define GQ_BBASE  (3 * GQ_BUF)               // Bs base (floats)
#define GQ_TOT    (6 * GQ_BUF)               // 61440 bytes

__global__ __launch_bounds__(256) void gemm_nt_bias(
    GemmArgs ga, int K, int lda, int ldb, int ldc)
{
    extern __shared__ float gsm[];
    const int z = blockIdx.z;
    const float* A    = ga.A[z];
    const float* Bm   = ga.W[z];
    const float* bias = ga.bias[z];
    float*       C    = ga.C[z];
    const float  alpha = ga.alpha[z];

    const int tid = threadIdx.x;
    const int lane = tid & 31, w = tid >> 5;
    const int wm = w & 1, wn = w >> 1;
    const int lr = lane >> 2, lc = lane & 3;
    const int bm = blockIdx.y * 128, bn = blockIdx.x * 128;
    const int row = tid >> 1, half = tid & 1;

    const float* Ag = A + (size_t)(bm + row) * lda + half * 8;
    const float* Bg = Bm + (size_t)(bn + row) * ldb + half * 8;
    const unsigned daBase = smem_u32(&gsm[row * GQ_STRIDE + half * 8]);
    const unsigned dbBase = smem_u32(&gsm[GQ_BBASE + row * GQ_STRIDE + half * 8]);
    const unsigned bufStride = GQ_BUF * 4;

#define G_STAGE(kc, buf)                                                   \
    do {                                                                   \
        unsigned da = daBase + (buf) * bufStride;                          \
        unsigned db = dbBase + (buf) * bufStride;                          \
        CP16(da,      Ag + (kc) * 16);                                     \
        CP16(da + 16, Ag + (kc) * 16 + 4);                                 \
        CP16(db,      Bg + (kc) * 16);                                     \
        CP16(db + 16, Bg + (kc) * 16 + 4);                                 \
        CP_COMMIT();                                                       \
    } while (0)

    float acc[4][4][4] = {};

    const int NC = K >> 4;
    G_STAGE(0, 0);
    G_STAGE(1, 1);

    for (int kc = 0; kc < NC; kc++) {
        const int buf = kc % 3;
        if (kc + 1 < NC) CP_WAIT(1); else CP_WAIT(0);
        __syncthreads();
        // stage 2 ahead into buffer (kc+2)%3 (last read at iter kc-1,
        // protected by the sync above)
        if (kc + 2 < NC) G_STAGE(kc + 2, (kc + 2) % 3);

        const float* As_ = gsm + buf * GQ_BUF;
        const float* Bs_ = gsm + GQ_BBASE + buf * GQ_BUF;
#pragma unroll
        for (int kt = 0; kt < 2; kt++) {
            const int kk = kt * 8;
            unsigned af[4][4], bf[4][2];
#pragma unroll
            for (int i = 0; i < 4; i++) {
                int mr = wm * 64 + i * 16 + lr;
                af[i][0] = cvt_tf32(As_[mr * GQ_STRIDE + kk + lc]);
                af[i][1] = cvt_tf32(As_[(mr + 8) * GQ_STRIDE + kk + lc]);
                af[i][2] = cvt_tf32(As_[mr * GQ_STRIDE + kk + 4 + lc]);
                af[i][3] = cvt_tf32(As_[(mr + 8) * GQ_STRIDE + kk + 4 + lc]);
            }
#pragma unroll
            for (int j = 0; j < 4; j++) {
                int nr = wn * 32 + j * 8 + lr;
                bf[j][0] = cvt_tf32(Bs_[nr * GQ_STRIDE + kk + lc]);
                bf[j][1] = cvt_tf32(Bs_[nr * GQ_STRIDE + kk + 4 + lc]);
            }
#pragma unroll
            for (int i = 0; i < 4; i++)
#pragma unroll
                for (int j = 0; j < 4; j++)
                    mma8(acc[i][j], af[i], bf[j]);
        }
    }
#undef G_STAGE

#pragma unroll
    for (int j = 0; j < 4; j++) {
        int col = bn + wn * 32 + j * 8 + lc * 2;
        float b0v = bias[col], b1v = bias[col + 1];
#pragma unroll
        for (int i = 0; i < 4; i++) {
            int r0 = bm + wm * 64 + i * 16 + lr;
            *(float2*)(C + (size_t)r0 * ldc + col) =
                make_float2(alpha * (acc[i][j][0] + b0v), alpha * (acc[i][j][1] + b1v));
            *(float2*)(C + (size_t)(r0 + 8) * ldc + col) =
                make_float2(alpha * (acc[i][j][2] + b0v), alpha * (acc[i][j][3] + b1v));
        }
    }
}

// ---------------------------------------------------------------------------
// Fused attention (R15 version, unchanged):
// Phase 0: online stats over recomputed scores (registers).
// Phase 1: recompute scores, p = exp(clamp(v)-m)*inv (mask->0), write p once,
//          Ps smem bounce, Ctx += P @ V.
// Layout (floats): Q[128][68] | Ps[64][136] | K[64][68] | V[64][72] |
//                  st float2[128] | mk char[2048]
// ---------------------------------------------------------------------------
#define FZ_Q  0
#define FZ_P  8704
#define FZ_K  17408
#define FZ_V  21760
#define FZ_ST 26368
#define FZ_MK 26624
#define FZ_TOT 27136

__global__ __launch_bounds__(256, 2) void attn_fused(
    const float* __restrict__ Qp, const float* __restrict__ Kp,
    const float* __restrict__ Vp, const int* __restrict__ mask,
    float* __restrict__ P, float* __restrict__ Ctx)
{
    extern __shared__ float sm[];
    const int bh = blockIdx.y, b = bh >> 4, h = bh & 15;
    const int tid = threadIdx.x;
    const int lane = tid & 31, w = tid >> 5;
    const int wm = w & 1, wn = w >> 1;
    const int lr = lane >> 2, lc = lane & 3;
    const int bm = blockIdx.x * 128;
    const unsigned smb = smem_u32(sm);

    // mask bytes for all S
    {
        char* mk = (char*)(sm + FZ_MK);
        const int* mg = mask + (size_t)b * S_;
#pragma unroll
        for (int u = 0; u < 8; u++) {
            int i = u * 256 + tid;
            mk[i] = (mg[i] != 0);
        }
    }

    const float* Kg = Kp + (size_t)b * S_ * E_ + h * DH_;
    const float* Vg = Vp + (size_t)b * S_ * E_ + h * DH_;

    // stage Q (rows bm..bm+127, 64 k) raw row-major [128][68]
    {
        const float* Qg = Qp + (size_t)b * T_ * E_ + (size_t)bm * E_ + h * DH_;
#pragma unroll
        for (int u = 0; u < 8; u++) {
            int lin = u * 256 + tid;
            int r_ = lin >> 4, sg = lin & 15;
            CP16(smb + (FZ_Q + r_ * 68 + sg * 4) * 4,
                 Qg + (size_t)r_ * E_ + sg * 4);
        }
        CP_COMMIT();
    }

#define STAGE_KB(cb, off, str)                                             \
    do {                                                                   \
        _Pragma("unroll")                                                  \
        for (int u = 0; u < 4; u++) {                                      \
            int lin = u * 256 + tid;                                       \
            int r_ = lin >> 4, sg = lin & 15;                              \
            CP16(smb + ((off) + r_ * (str) + sg * 4) * 4,                  \
                 Kg + (size_t)((cb) * 64 + r_) * E_ + sg * 4);             \
        }                                                                  \
        CP_COMMIT();                                                       \
    } while (0)

#define STAGE_V(cb)                                                        \
    do {                                                                   \
        _Pragma("unroll")                                                  \
        for (int u = 0; u < 4; u++) {                                      \
            int lin = u * 256 + tid;                                       \
            int r_ = lin >> 4, sg = lin & 15;                              \
            CP16(smb + (FZ_V + r_ * 72 + sg * 4) * 4,                      \
                 Vg + (size_t)((cb) * 64 + r_) * E_ + sg * 4);             \
        }                                                                  \
        CP_COMMIT();                                                       \
    } while (0)

    const char* mk = (const char*)(sm + FZ_MK);
    const float* Qb = sm + FZ_Q;

#define SCORE_MMA(Kb_, kstr_, accs)                                        \
    do {                                                                   \
        _Pragma("unroll")                                                  \
        for (int kt = 0; kt < 8; kt++) {                                   \
            const int kk = kt * 8;                                         \
            unsigned af[4][4], bf[2][2];                                   \
            _Pragma("unroll")                                              \
            for (int i = 0; i < 4; i++) {                                  \
                int mr = wm * 64 + i * 16 + lr;                            \
                af[i][0] = cvt_tf32(Qb[mr * 68 + kk + lc]);                \
                af[i][1] = cvt_tf32(Qb[(mr + 8) * 68 + kk + lc]);          \
                af[i][2] = cvt_tf32(Qb[mr * 68 + kk + 4 + lc]);            \
                af[i][3] = cvt_tf32(Qb[(mr + 8) * 68 + kk + 4 + lc]);      \
            }                                                              \
            _Pragma("unroll")                                              \
            for (int j = 0; j < 2; j++) {                                  \
                int nb = wn * 16 + j * 8 + lr;                             \
                bf[j][0] = cvt_tf32((Kb_)[nb * (kstr_) + kk + lc]);        \
                bf[j][1] = cvt_tf32((Kb_)[nb * (kstr_) + kk + 4 + lc]);    \
            }                                                              \
            _Pragma("unroll")                                              \
            for (int i = 0; i < 4; i++)                                    \
                _Pragma("unroll")                                          \
                for (int j = 0; j < 2; j++)                                \
                    mma8(accs[i][j], af[i], bf[j]);                        \
        }                                                                  \
    } while (0)

    // ------------------ Phase 0: stats (online, registers) ------------------
    STAGE_KB(0, FZ_K, 68);
    STAGE_KB(1, FZ_V, 72);

    float m_run[4][2], s_run[4][2];
#pragma unroll
    for (int i = 0; i < 4; i++) {
        m_run[i][0] = -INFINITY; m_run[i][1] = -INFINITY;
        s_run[i][0] = 0.f;       s_run[i][1] = 0.f;
    }

    for (int cb = 0; cb < 32; cb++) {
        CP_WAIT(1);
        __syncthreads();
        const float* Kb = sm + ((cb & 1) ? FZ_V : FZ_K);
        const int kstr  = (cb & 1) ? 72 : 68;

        float acc_s[4][2][4] = {};
        SCORE_MMA(Kb, kstr, acc_s);

#pragma unroll
        for (int i = 0; i < 4; i++) {
#pragma unroll
            for (int hh = 0; hh < 2; hh++) {
                int lcol0 = wn * 16 + lc * 2;
                int g0 = cb * 64 + lcol0, g1 = cb * 64 + lcol0 + 8;
                bool k0 = mk[g0] != 0, k1 = mk[g0 + 1] != 0;
                bool k2 = mk[g1] != 0, k3 = mk[g1 + 1] != 0;
                float v0 = k0 ? fminf(fmaxf(acc_s[i][0][hh * 2],     -CLAMP_V), CLAMP_V) : -INFINITY;
                float v1 = k1 ? fminf(fmaxf(acc_s[i][0][hh * 2 + 1], -CLAMP_V), CLAMP_V) : -INFINITY;
                float v2 = k2 ? fminf(fmaxf(acc_s[i][1][hh * 2],     -CLAMP_V), CLAMP_V) : -INFINITY;
                float v3 = k3 ? fminf(fmaxf(acc_s[i][1][hh * 2 + 1], -CLAMP_V), CLAMP_V) : -INFINITY;
                float bmax = fmaxf(fmaxf(v0, v1), fmaxf(v2, v3));
                if (bmax != -INFINITY) {
                    float nm = fmaxf(m_run[i][hh], bmax);
                    float sc = (m_run[i][hh] == -INFINITY) ? 0.f
                               : s_run[i][hh] * __expf(m_run[i][hh] - nm);
                    s_run[i][hh] = sc + __expf(v0 - nm) + __expf(v1 - nm)
                                      + __expf(v2 - nm) + __expf(v3 - nm);
                    m_run[i][hh] = nm;
                }
            }
        }
        __syncthreads();
        if (cb + 2 < 32) STAGE_KB(cb + 2, (cb & 1) ? FZ_V : FZ_K, (cb & 1) ? 72 : 68);
    }
    CP_WAIT(0);

    // merge across lc lanes (shfl), then across wn warps (smem = Ps region)
    {
        float* red_m = sm + FZ_P;          // [4][128]
        float* red_s = sm + FZ_P + 512;    // [4][128]
#pragma unroll
        for (int i = 0; i < 4; i++) {
#pragma unroll
            for (int hh = 0; hh < 2; hh++) {
                float m = m_run[i][hh], s = s_run[i][hh];
#pragma unroll
                for (int off = 1; off <= 2; off <<= 1) {
                    softmax_merge(m, s, __shfl_xor_sync(0xffffffffu, m, off),
                                        __shfl_xor_sync(0xffffffffu, s, off));
                }
                if (lc == 0) {
                    int rl = wm * 64 + i * 16 + lr + hh * 8;
                    red_m[wn * 128 + rl] = m;
                    red_s[wn * 128 + rl] = s;
                }
            }
        }
        __syncthreads();
        if (tid < 128) {
            float m = red_m[tid], s = red_s[tid];
            softmax_merge(m, s, red_m[128 + tid], red_s[128 + tid]);
            softmax_merge(m, s, red_m[256 + tid], red_s[256 + tid]);
            softmax_merge(m, s, red_m[384 + tid], red_s[384 + tid]);
            ((float2*)(sm + FZ_ST))[tid] = make_float2(m, 1.f / s);
        }
        __syncthreads();
    }

    // ------------------ Phase 1: p-write + PV --------------------
    STAGE_KB(0, FZ_K, 68);
    STAGE_V(0);

    float* Pg = P + (size_t)bh * T_ * S_;
    const float2* st = (const float2*)(sm + FZ_ST);

    float acc_c[4][2][4] = {};

    for (int cb = 0; cb < 32; cb++) {
        CP_WAIT(0);
        __syncthreads();

        float acc_s[4][2][4] = {};
        SCORE_MMA(sm + FZ_K, 68, acc_s);

        // epilogue: p = exp(clamp(v)-m)*inv (mask->0); write attn + Ps smem
        {
            float* Pb = sm + FZ_P;
#pragma unroll
            for (int i = 0; i < 4; i++) {
                int rl = wm * 64 + i * 16 + lr;
                float2 s0 = st[rl], s1 = st[rl + 8];
                float m0 = (s0.x == -INFINITY) ? 0.f : s0.x;
                float m1 = (s1.x == -INFINITY) ? 0.f : s1.x;
#pragma unroll
                for (int j = 0; j < 2; j++) {
                    int lcol = wn * 16 + j * 8 + lc * 2;
                    int gcol = cb * 64 + lcol;
                    bool k0 = mk[gcol] != 0, k1 = mk[gcol + 1] != 0;
                    float v00 = fminf(fmaxf(acc_s[i][j][0], -CLAMP_V), CLAMP_V);
                    float v01 = fminf(fmaxf(acc_s[i][j][1], -CLAMP_V), CLAMP_V);
                    float v10 = fminf(fmaxf(acc_s[i][j][2], -CLAMP_V), CLAMP_V);
                    float v11 = fminf(fmaxf(acc_s[i][j][3], -CLAMP_V), CLAMP_V);
                    float p00 = k0 ? __expf(v00 - m0) * s0.y : 0.f;
                    float p01 = k1 ? __expf(v01 - m0) * s0.y : 0.f;
                    float p10 = k0 ? __expf(v10 - m1) * s1.y : 0.f;
                    float p11 = k1 ? __expf(v11 - m1) * s1.y : 0.f;
                    *(float2*)(Pg + (size_t)(bm + rl) * S_ + gcol)     = make_float2(p00, p01);
                    *(float2*)(Pg + (size_t)(bm + rl + 8) * S_ + gcol) = make_float2(p10, p11);
                    Pb[lcol * 136 + rl]           = tf32f(p00);
                    Pb[(lcol + 1) * 136 + rl]     = tf32f(p01);
                    Pb[lcol * 136 + rl + 8]       = tf32f(p10);
                    Pb[(lcol + 1) * 136 + rl + 8] = tf32f(p11);
                }
            }
        }
        __syncthreads();   // Ps ready; K region dead

        if (cb + 1 < 32) STAGE_KB(cb + 1, FZ_K, 68);

        // PV: Ctx += P(128x64) @ V(64x64)
        {
            const float* Pb = sm + FZ_P;
            const float* Vb = sm + FZ_V;
#pragma unroll
            for (int kt8 = 0; kt8 < 8; kt8++) {
                const int kk = kt8 * 8;
                unsigned af[4][4], bf[2][2];
#pragma unroll
                for (int i = 0; i < 4; i++) {
                    int mb = wm * 64 + i * 16 + lr;
                    af[i][0] = __float_as_uint(Pb[(kk + lc) * 136 + mb]);
                    af[i][1] = __float_as_uint(Pb[(kk + lc) * 136 + mb + 8]);
                    af[i][2] = __float_as_uint(Pb[(kk + 4 + lc) * 136 + mb]);
                    af[i][3] = __float_as_uint(Pb[(kk + 4 + lc) * 136 + mb + 8]);
                }
#pragma unroll
                for (int j = 0; j < 2; j++) {
                    int nb = wn * 16 + j * 8 + lr;
                    bf[j][0] = cvt_tf32(Vb[(kk + lc) * 72 + nb]);
                    bf[j][1] = cvt_tf32(Vb[(kk + 4 + lc) * 72 + nb]);
                }
#pragma unroll
                for (int i = 0; i < 4; i++)
#pragma unroll
                    for (int j = 0; j < 2; j++)
                        mma8(acc_c[i][j], af[i], bf[j]);
            }
        }
        __syncthreads();   // V, Ps free

        if (cb + 1 < 32) STAGE_V(cb + 1);
    }
#undef STAGE_KB
#undef STAGE_V
#undef SCORE_MMA

    // Ctx epilogue
    {
        float* Cg = Ctx + (size_t)b * T_ * E_ + h * DH_;
#pragma unroll
        for (int j = 0; j < 2; j++) {
            int col = wn * 16 + j * 8 + lc * 2;
#pragma unroll
            for (int i = 0; i < 4; i++) {
                int r0 = bm + wm * 64 + i * 16 + lr;
                *(float2*)(Cg + (size_t)r0 * E_ + col) =
                    make_float2(acc_c[i][j][0], acc_c[i][j][1]);
                *(float2*)(Cg + (size_t)(r0 + 8) * E_ + col) =
                    make_float2(acc_c[i][j][2], acc_c[i][j][3]);
            }
        }
    }
}

// ---------------------------------------------------------------------------
extern "C" void kernel_launch(void* const* d_in, const int* in_sizes, int n_in,
                              void* d_out, int out_size)
{
    const float* q    = (const float*)d_in[0];
    const float* k    = (const float*)d_in[1];
    const float* v    = (const float*)d_in[2];
    const int*   mask = (const int*)d_in[3];
    const float* Wq   = (const float*)d_in[4];
    const float* bq   = (const float*)d_in[5];
    const float* Wk   = (const float*)d_in[6];
    const float* bk   = (const float*)d_in[7];
    const float* Wv   = (const float*)d_in[8];
    const float* bv   = (const float*)d_in[9];
    const float* Wo   = (const float*)d_in[10];
    const float* bo   = (const float*)d_in[11];

    float* out  = (float*)d_out;
    float* attn = out + (size_t)B_ * T_ * E_;

    float *Qp, *Kp, *Vp, *Ctx;
    cudaGetSymbolAddress((void**)&Qp, g_Qp);
    cudaGetSymbolAddress((void**)&Kp, g_Kp);
    cudaGetSymbolAddress((void**)&Vp, g_Vp);
    cudaGetSymbolAddress((void**)&Ctx, g_ctx);

    cudaFuncSetAttribute(gemm_nt_bias,
                         cudaFuncAttributeMaxDynamicSharedMemorySize,
                         GQ_TOT * 4);
    cudaFuncSetAttribute(attn_fused,
                         cudaFuncAttributeMaxDynamicSharedMemorySize,
                         FZ_TOT * 4);

    dim3 gq(E_ / 128, (B_ * T_) / 128, 3);   // QKV fused: (8, 32, 3)
    GemmArgs g1;
    g1.A[0] = q;  g1.W[0] = Wq; g1.bias[0] = bq; g1.C[0] = Qp; g1.alpha[0] = SCALE_;
    g1.A[1] = k;  g1.W[1] = Wk; g1.bias[1] = bk; g1.C[1] = Kp; g1.alpha[1] = 1.0f;
    g1.A[2] = v;  g1.W[2] = Wv; g1.bias[2] = bv; g1.C[2] = Vp; g1.alpha[2] = 1.0f;
    gemm_nt_bias<<<gq, 256, GQ_TOT * 4>>>(g1, E_, E_, E_, E_);

    attn_fused<<<dim3(T_ / 128, B_ * H_), 256, FZ_TOT * 4>>>(
        Qp, Kp, Vp, mask, attn, Ctx);

    GemmArgs g2;
    g2.A[0] = Ctx; g2.W[0] = Wo; g2.bias[0] = bo; g2.C[0] = out; g2.alpha[0] = 1.0f;
    g2.A[1] = Ctx; g2.W[1] = Wo; g2.bias[1] = bo; g2.C[1] = out; g2.alpha[1] = 1.0f;
    g2.A[2] = Ctx; g2.W[2] = Wo; g2.bias[2] = bo; g2.C[2] = out; g2.alpha[2] = 1.0f;
    gemm_nt_bias<<<dim3(E_ / 128, (B_ * T_) / 128, 1), 256, GQ_TOT * 4>>>(g2, E_, E_, E_, E_);
}